// round 7
// baseline (speedup 1.0000x reference)
#include <cuda_runtime.h>
#include <cuda_bf16.h>
#include <cstdint>
#include <cstddef>

#define BB   2
#define SS   1024
#define LL   2
#define HH   8
#define DD   512
#define DFF  2048
#define DKH  64
#define NTOK (BB*SS)      // 2048
#define NC   (SS/64)      // 16
#define BH   (BB*HH)      // 16
#define QSTR 1536
#define EPSF 1e-5f

typedef __nv_bfloat16 bf16;

// ---------------- scratch (device globals; no allocation) ----------------
__device__ __align__(128) float g_x   [NTOK*DD];
__device__ __align__(128) float g_tmp [NTOK*DD];
__device__ __align__(128) float g_qkv [NTOK*QSTR];
__device__ __align__(128) float g_kvc [BH*NC*DKH*DKH];
__device__ __align__(128) float g_st  [BH*NC*DKH*DKH];
__device__ __align__(128) bf16  g_xh  [NTOK*DD];
__device__ __align__(128) bf16  g_xl  [NTOK*DD];
__device__ __align__(128) bf16  g_atth[NTOK*DD];
__device__ __align__(128) bf16  g_attl[NTOK*DD];
__device__ __align__(128) bf16  g_ffh [NTOK*DFF];
__device__ __align__(128) bf16  g_ffl [NTOK*DFF];
#define WT_QKV 0
#define WT_O   (QSTR*DD)
#define WT_1   (WT_O + DD*DD)
#define WT_2   (WT_1 + DFF*DD)
#define WT_LAYER (WT_2 + DD*DFF)
__device__ __align__(128) bf16  g_wth [LL*WT_LAYER];
__device__ __align__(128) bf16  g_wtl [LL*WT_LAYER];
__device__ __align__(128) float g_bqkv[LL*QSTR];

// ============================ helpers ==================================
__device__ __forceinline__ void split_bf16(float v, bf16& h, bf16& l){
    h = __float2bfloat16(v);
    l = __float2bfloat16(v - __bfloat162float(h));
}
__device__ __forceinline__ uint32_t smem_u32(const void* p){
    uint32_t r;
    asm("{ .reg .u64 t; cvta.to.shared.u64 t, %1; cvt.u32.u64 %0, t; }" : "=r"(r) : "l"(p));
    return r;
}
__device__ __forceinline__ void mma_bf16(float* d, const uint32_t* a, const uint32_t* b){
    asm volatile(
        "mma.sync.aligned.m16n8k16.row.col.f32.bf16.bf16.f32 "
        "{%0,%1,%2,%3}, {%4,%5,%6,%7}, {%8,%9}, {%0,%1,%2,%3};\n"
        : "+f"(d[0]), "+f"(d[1]), "+f"(d[2]), "+f"(d[3])
        : "r"(a[0]), "r"(a[1]), "r"(a[2]), "r"(a[3]), "r"(b[0]), "r"(b[1]));
}
__device__ __forceinline__ void ldm4(uint32_t* r, uint32_t a){
    asm volatile("ldmatrix.sync.aligned.m8n8.x4.shared.b16 {%0,%1,%2,%3}, [%4];"
        : "=r"(r[0]), "=r"(r[1]), "=r"(r[2]), "=r"(r[3]) : "r"(a));
}
__device__ __forceinline__ void cp16(uint32_t dst, const void* src){
    asm volatile("cp.async.cg.shared.global [%0], [%1], 16;" :: "r"(dst), "l"(src));
}
#define CP_COMMIT() asm volatile("cp.async.commit_group;" ::: "memory")
#define CP_WAIT1()  asm volatile("cp.async.wait_group 1;" ::: "memory")

// ============== bf16 3-term GEMM: C[M,N] = A[M,K] @ B^T ====================
// A?,B?: bf16 [rows,K] row-major (hi/lo split). D = AhBh + AlBh + AhBl.
// Tiles: BM x 128, K-chunk 32, 8 warps, cp.async double buffer, ldmatrix frags.
// EPI: 0 = +bias -> fp32 C;  1 = +bias,relu -> split bf16;  2 = +bias+R -> fp32 C
template<int EPI, int BM>
__global__ void __launch_bounds__(256, 1)
bf16_gemm(const bf16* __restrict__ Ah, const bf16* __restrict__ Al,
          const bf16* __restrict__ Bh, const bf16* __restrict__ Bl,
          const float* __restrict__ bias, const float* __restrict__ R,
          float* __restrict__ C, bf16* __restrict__ Ch, bf16* __restrict__ Cl,
          int M, int N, int K)
{
    constexpr int MT     = BM / 32;          // warp m-subtiles
    constexpr int ABYTES = BM * 64;          // one A subtile (h or l)
    constexpr int BBYTES = 128 * 64;         // one B subtile
    constexpr int CHUNK  = 2*ABYTES + 2*BBYTES;
    extern __shared__ __align__(16) char dsm[];
    const uint32_t sbase = smem_u32(dsm);

    const int tid = threadIdx.x, lane = tid & 31, wid = tid >> 5;
    const int wm  = (wid >> 2) * (BM / 2), wn = (wid & 3) * 32;
    const int m0  = blockIdx.y * BM, n0 = blockIdx.x * 128;
    const int nch = K >> 5;

    float acc[MT][4][4] = {};

    auto load_chunk = [&](int ch){
        const uint32_t bb = sbase + (ch & 1) * CHUNK;
        const int koff = ch * 32;
#pragma unroll
        for (int i = 0; i < ABYTES/16/256; ++i){
            const int u = tid + i * 256, row = u >> 2, g = u & 3;
            const uint32_t dst = bb + row*64 + ((g ^ ((row >> 1) & 3)) << 4);
            const size_t so = (size_t)(m0 + row) * K + koff + g * 8;
            cp16(dst,          Ah + so);
            cp16(dst + ABYTES, Al + so);
        }
#pragma unroll
        for (int i = 0; i < 2; ++i){
            const int u = tid + i * 256, row = u >> 2, g = u & 3;
            const uint32_t dst = bb + 2*ABYTES + row*64 + ((g ^ ((row >> 1) & 3)) << 4);
            const size_t so = (size_t)(n0 + row) * K + koff + g * 8;
            cp16(dst,          Bh + so);
            cp16(dst + BBYTES, Bl + so);
        }
    };

    auto compute = [&](int buf){
        const uint32_t bb = sbase + buf * CHUNK;
        const uint32_t aH = bb, aL = bb + ABYTES;
        const uint32_t bH = bb + 2*ABYTES, bL = bb + 2*ABYTES + BBYTES;
#pragma unroll
        for (int ks = 0; ks < 2; ++ks){
            const int g = ks * 2 + (lane >> 4);
            uint32_t bh[4][2], bl[4][2];
#pragma unroll
            for (int np = 0; np < 2; ++np){
                const int n = wn + np*16 + (lane & 15);
                const uint32_t off = n*64 + ((g ^ ((n >> 1) & 3)) << 4);
                uint32_t t[4];
                ldm4(t, bH + off);
                bh[2*np][0]=t[0]; bh[2*np][1]=t[2]; bh[2*np+1][0]=t[1]; bh[2*np+1][1]=t[3];
                ldm4(t, bL + off);
                bl[2*np][0]=t[0]; bl[2*np][1]=t[2]; bl[2*np+1][0]=t[1]; bl[2*np+1][1]=t[3];
            }
#pragma unroll
            for (int mt = 0; mt < MT; ++mt){
                const int r = wm + mt*16 + (lane & 15);
                const uint32_t off = r*64 + ((g ^ ((r >> 1) & 3)) << 4);
                uint32_t ah[4], al[4];
                ldm4(ah, aH + off);
                ldm4(al, aL + off);
#pragma unroll
                for (int nt = 0; nt < 4; ++nt){
                    mma_bf16(acc[mt][nt], ah, bh[nt]);
                    mma_bf16(acc[mt][nt], al, bh[nt]);
                    mma_bf16(acc[mt][nt], ah, bl[nt]);
                }
            }
        }
    };

    load_chunk(0); CP_COMMIT();
    load_chunk(1); CP_COMMIT();
    for (int ch = 0; ch < nch; ++ch){
        CP_WAIT1();
        __syncthreads();
        compute(ch & 1);
        __syncthreads();
        if (ch + 2 < nch) load_chunk(ch + 2);
        CP_COMMIT();
    }

    // epilogue: direct from accumulator fragments
#pragma unroll
    for (int mt = 0; mt < MT; ++mt){
#pragma unroll
        for (int nt = 0; nt < 4; ++nt){
            const int col = n0 + wn + nt*8 + (lane & 3) * 2;
            const float b0 = bias[col], b1 = bias[col + 1];
#pragma unroll
            for (int hf = 0; hf < 2; ++hf){
                const int row = m0 + wm + mt*16 + (lane >> 2) + hf*8;
                float v0 = acc[mt][nt][hf*2 + 0] + b0;
                float v1 = acc[mt][nt][hf*2 + 1] + b1;
                const size_t o = (size_t)row * N + col;
                if (EPI == 0){
                    *(float2*)&C[o] = make_float2(v0, v1);
                } else if (EPI == 1){
                    v0 = fmaxf(v0, 0.f); v1 = fmaxf(v1, 0.f);
                    bf16 h0, l0, h1, l1;
                    split_bf16(v0, h0, l0); split_bf16(v1, h1, l1);
                    *(__nv_bfloat162*)&Ch[o] = __nv_bfloat162(h0, h1);
                    *(__nv_bfloat162*)&Cl[o] = __nv_bfloat162(l0, l1);
                } else {
                    const float2 rr = *(const float2*)&R[o];
                    *(float2*)&C[o] = make_float2(v0 + rr.x, v1 + rr.y);
                }
            }
        }
    }
}

// ------- batched weight transpose+split: all 6 matrices, both layers -------
__global__ void transpose_split_all(
    const float* __restrict__ Wq, const float* __restrict__ Wk,
    const float* __restrict__ Wv, const float* __restrict__ Wo,
    const float* __restrict__ W1, const float* __restrict__ W2,
    bf16* __restrict__ wth, bf16* __restrict__ wtl)
{
    const int layer = blockIdx.y;
    int t = blockIdx.x;
    const float* S; int K, N; size_t doff;
    if (t < 1024){
        const int m = t >> 8; t &= 255;
        K = DD; N = DD;
        const float* s4[4] = {Wq, Wk, Wv, Wo};
        S = s4[m] + (size_t)layer * DD * DD;
        doff = (size_t)layer * WT_LAYER + (m < 3 ? (size_t)(WT_QKV + m*DD*DD) : (size_t)WT_O);
    } else if (t < 2048){
        t -= 1024; K = DD; N = DFF;
        S = W1 + (size_t)layer * DD * DFF;
        doff = (size_t)layer * WT_LAYER + WT_1;
    } else {
        t -= 2048; K = DFF; N = DD;
        S = W2 + (size_t)layer * DFF * DD;
        doff = (size_t)layer * WT_LAYER + WT_2;
    }
    const int ntx = N / 32;
    const int n0 = (t % ntx) * 32, k0 = (t / ntx) * 32;

    __shared__ float tt[32][33];
    const int x = threadIdx.x, y = threadIdx.y;   // 32 x 8
#pragma unroll
    for (int i = 0; i < 32; i += 8)
        tt[y + i][x] = S[(size_t)(k0 + y + i) * N + n0 + x];
    __syncthreads();
#pragma unroll
    for (int i = 0; i < 32; i += 8){
        const float v = tt[x][y + i];
        bf16 h, l; split_bf16(v, h, l);
        const size_t o = doff + (size_t)(n0 + y + i) * K + k0 + x;
        wth[o] = h; wtl[o] = l;
    }
}

// ---------------- split fp32 -> bf16 hi/lo ---------------------------------
__global__ void split_kernel(const float* __restrict__ X, bf16* __restrict__ Xh,
                             bf16* __restrict__ Xl)
{
    const int t = blockIdx.x * 256 + threadIdx.x;
    const float4 v = ((const float4*)X)[t];
    bf16 h0,l0,h1,l1,h2,l2,h3,l3;
    split_bf16(v.x,h0,l0); split_bf16(v.y,h1,l1);
    split_bf16(v.z,h2,l2); split_bf16(v.w,h3,l3);
    ((__nv_bfloat162*)Xh)[t*2+0] = __nv_bfloat162(h0,h1);
    ((__nv_bfloat162*)Xh)[t*2+1] = __nv_bfloat162(h2,h3);
    ((__nv_bfloat162*)Xl)[t*2+0] = __nv_bfloat162(l0,l1);
    ((__nv_bfloat162*)Xl)[t*2+1] = __nv_bfloat162(l2,l3);
}

__global__ void concat_bias(const float* __restrict__ bq, const float* __restrict__ bk,
                            const float* __restrict__ bv, float* __restrict__ dst)
{
    const int layer = blockIdx.y;
    const int t = blockIdx.x * 256 + threadIdx.x;
    float* d = dst + (size_t)layer * QSTR;
    if (t < 512)       d[t] = bq[layer*DD + t];
    else if (t < 1024) d[t] = bk[layer*DD + t - 512];
    else if (t < 1536) d[t] = bv[layer*DD + t - 1024];
}

// ---------------- LayerNorm (+ optional bf16 split outputs) ----------------
__global__ void ln_kernel(const float* __restrict__ X, const float* __restrict__ g,
                          const float* __restrict__ b, float* __restrict__ Y,
                          bf16* __restrict__ Yh, bf16* __restrict__ Yl)
{
    const int row = blockIdx.x;
    const int tid = threadIdx.x;
    const float* x = X + (size_t)row * DD;
    __shared__ float rs[256], rs2[256];
    float s = 0.f, s2 = 0.f;
    for (int j = tid; j < DD; j += 256) { float v = x[j]; s += v; s2 += v*v; }
    rs[tid] = s; rs2[tid] = s2;
    __syncthreads();
    for (int o = 128; o > 0; o >>= 1) {
        if (tid < o) { rs[tid] += rs[tid+o]; rs2[tid] += rs2[tid+o]; }
        __syncthreads();
    }
    const float m    = rs[0] * (1.f/DD);
    const float var  = rs2[0] * (1.f/DD) - m*m;
    const float rstd = rsqrtf(var + EPSF);
    for (int j = tid; j < DD; j += 256){
        const float v = (x[j] - m) * rstd * g[j] + b[j];
        Y[(size_t)row * DD + j] = v;
        if (Yh){
            bf16 h, l; split_bf16(v, h, l);
            Yh[(size_t)row * DD + j] = h;
            Yl[(size_t)row * DD + j] = l;
        }
    }
}

// ---------------- attention kernel 1: per-chunk K^T V [64x64] --------------
__global__ void attn_kvc_kernel(const float* __restrict__ QKV, float* __restrict__ kvc)
{
    __shared__ float ks[64][68], vs[64][68];
    const int blk = blockIdx.x;
    const int bh  = blk >> 4, c = blk & 15;
    const int b   = bh >> 3,  h = bh & 7;
    const int tid = threadIdx.x;
    const int j   = tid >> 2, base = (tid & 3) * 16;

    const size_t tok = (size_t)(b*SS + c*64 + j) * QSTR + h*DKH + base;
    const float* Kx = QKV + DD;
    const float* Vx = QKV + 2*DD;
#pragma unroll
    for (int u = 0; u < 4; ++u) {
        *(float4*)&ks[j][base + u*4] = *(const float4*)&Kx[tok + u*4];
        *(float4*)&vs[j][base + u*4] = *(const float4*)&Vx[tok + u*4];
    }
    __syncthreads();

    const int p = tid >> 2, qb = tid & 3;
    float acc[16] = {};
    for (int jj = 0; jj < 64; ++jj) {
        const float kp = ks[jj][p];
#pragma unroll
        for (int i = 0; i < 16; ++i) acc[i] += kp * vs[jj][qb + 4*i];
    }
    float* out = kvc + (size_t)blk * 4096 + p * 64;
#pragma unroll
    for (int i = 0; i < 16; ++i) out[qb + 4*i] = acc[i];
}

// ---------------- attention kernel 2: exclusive prefix over chunks ---------
__global__ void attn_prefix_kernel(const float* __restrict__ kvc, float* __restrict__ st)
{
    const int bh = blockIdx.x >> 4, r = blockIdx.x & 15;
    const int e  = threadIdx.x + r * 256;
    const size_t base = (size_t)bh * NC * 4096 + e;
    float v[NC];
#pragma unroll
    for (int c = 0; c < NC; ++c) v[c] = kvc[base + (size_t)c * 4096];
    float run = 0.f;
#pragma unroll
    for (int c = 0; c < NC; ++c) { st[base + (size_t)c * 4096] = run; run += v[c]; }
}

// ---------------- attention kernel 3: O = tril(QK^T)V + Q*state ------------
__global__ void attn_out_kernel(const float* __restrict__ QKV, const float* __restrict__ st,
                                bf16* __restrict__ Ath, bf16* __restrict__ Atl)
{
    extern __shared__ float sm[];
    float (*qs )[68] = (float(*)[68])sm;
    float (*ks )[68] = qs  + 64;
    float (*vs )[68] = ks  + 64;
    float (*ssm)[68] = vs  + 64;
    float (*sts)[68] = ssm + 64;

    const int blk = blockIdx.x;
    const int bh  = blk >> 4, c = blk & 15;
    const int b   = bh >> 3,  h = bh & 7;
    const int tid = threadIdx.x;
    const int row = tid >> 2, base = (tid & 3) * 16;

    const size_t tok = (size_t)(b*SS + c*64 + row) * QSTR + h*DKH + base;
    const float* stg = st + (size_t)blk * 4096 + row * 64 + base;
#pragma unroll
    for (int u = 0; u < 4; ++u) {
        *(float4*)&qs [row][base + u*4] = *(const float4*)&QKV[tok + u*4];
        *(float4*)&ks [row][base + u*4] = *(const float4*)&QKV[tok + DD + u*4];
        *(float4*)&vs [row][base + u*4] = *(const float4*)&QKV[tok + 2*DD + u*4];
        *(float4*)&sts[row][base + u*4] = *(const float4*)&stg[u*4];
    }
    __syncthreads();

    const int i = tid >> 2, j0 = tid & 3;
    for (int jj = 0; jj < 16; ++jj) {
        const int j = j0 + 4*jj;
        float d = 0.f;
#pragma unroll
        for (int p = 0; p < 64; ++p) d += qs[i][p] * ks[j][p];
        ssm[i][j] = (j <= i) ? d : 0.f;
    }
    __syncthreads();

    float acc[16] = {};
    for (int jj = 0; jj < 64; ++jj) {
        const float sij = ssm[i][jj];
        const float qip = qs[i][jj];
#pragma unroll
        for (int dd = 0; dd < 16; ++dd) {
            acc[dd] += sij * vs[jj][j0 + 4*dd];
            acc[dd] += qip * sts[jj][j0 + 4*dd];
        }
    }
    const size_t outp = (size_t)(b*SS + c*64 + i) * DD + h*DKH;
#pragma unroll
    for (int dd = 0; dd < 16; ++dd){
        bf16 h2, l2; split_bf16(acc[dd], h2, l2);
        Ath[outp + j0 + 4*dd] = h2;
        Atl[outp + j0 + 4*dd] = l2;
    }
}

// ---------------------------------------------------------------------------
extern "C" void kernel_launch(void* const* d_in, const int* in_sizes, int n_in,
                              void* d_out, int out_size)
{
    const float* src = (const float*)d_in[0];
    const float* Wq  = (const float*)d_in[1];
    const float* bq  = (const float*)d_in[2];
    const float* Wk  = (const float*)d_in[3];
    const float* bk  = (const float*)d_in[4];
    const float* Wv  = (const float*)d_in[5];
    const float* bv  = (const float*)d_in[6];
    const float* Wo  = (const float*)d_in[7];
    const float* bo  = (const float*)d_in[8];
    const float* W1  = (const float*)d_in[9];
    const float* b1  = (const float*)d_in[10];
    const float* W2  = (const float*)d_in[11];
    const float* b2  = (const float*)d_in[12];
    const float* g1  = (const float*)d_in[13];
    const float* be1 = (const float*)d_in[14];
    const float* g2  = (const float*)d_in[15];
    const float* be2 = (const float*)d_in[16];
    const float* gf  = (const float*)d_in[17];
    const float* bef = (const float*)d_in[18];
    float* out = (float*)d_out;

    float *px, *ptmp, *pqkv, *pkvc, *pst, *pbqkv;
    bf16 *pxh, *pxl, *path, *patl, *pffh, *pffl, *pwth, *pwtl;
    cudaGetSymbolAddress((void**)&px,    g_x);
    cudaGetSymbolAddress((void**)&ptmp,  g_tmp);
    cudaGetSymbolAddress((void**)&pqkv,  g_qkv);
    cudaGetSymbolAddress((void**)&pkvc,  g_kvc);
    cudaGetSymbolAddress((void**)&pst,   g_st);
    cudaGetSymbolAddress((void**)&pbqkv, g_bqkv);
    cudaGetSymbolAddress((void**)&pxh,   g_xh);
    cudaGetSymbolAddress((void**)&pxl,   g_xl);
    cudaGetSymbolAddress((void**)&path,  g_atth);
    cudaGetSymbolAddress((void**)&patl,  g_attl);
    cudaGetSymbolAddress((void**)&pffh,  g_ffh);
    cudaGetSymbolAddress((void**)&pffl,  g_ffl);
    cudaGetSymbolAddress((void**)&pwth,  g_wth);
    cudaGetSymbolAddress((void**)&pwtl,  g_wtl);

    static const int ATTN_SMEM = 5 * 64 * 68 * 4;  // 87,040 B
    static const int SM128 = 2 * (2*128*64 + 2*128*64);  // 65536
    static const int SM64  = 2 * (2*64*64  + 2*128*64);  // 49152
    cudaFuncSetAttribute(attn_out_kernel, cudaFuncAttributeMaxDynamicSharedMemorySize, ATTN_SMEM);
    cudaFuncSetAttribute(bf16_gemm<0,128>, cudaFuncAttributeMaxDynamicSharedMemorySize, SM128);
    cudaFuncSetAttribute(bf16_gemm<1,128>, cudaFuncAttributeMaxDynamicSharedMemorySize, SM128);
    cudaFuncSetAttribute(bf16_gemm<2,64>,  cudaFuncAttributeMaxDynamicSharedMemorySize, SM64);

    // x = src (residual); split src for QKV GEMM
    cudaMemcpyAsync(px, src, (size_t)NTOK * DD * sizeof(float), cudaMemcpyDeviceToDevice, 0);
    split_kernel<<<NTOK*DD/4/256, 256>>>(src, pxh, pxl);

    // weight prep: single batched kernel + bias concat
    transpose_split_all<<<dim3(3072, LL), dim3(32, 8)>>>(Wq, Wk, Wv, Wo, W1, W2, pwth, pwtl);
    concat_bias<<<dim3(6, LL), 256>>>(bq, bk, bv, pbqkv);

    const dim3 gQKV(QSTR / 128, NTOK / 128);   // 12 x 16
    const dim3 gO  (DD   / 128, NTOK / 64);    // 4 x 32  (BM=64)
    const dim3 gDF (DFF  / 128, NTOK / 128);   // 16 x 16
    const dim3 blk(256);

    for (int i = 0; i < LL; ++i) {
        bf16* wh = pwth + (size_t)i * WT_LAYER;
        bf16* wl = pwtl + (size_t)i * WT_LAYER;
        const float* bov = bo + (size_t)i*DD;
        const float* b1v = b1 + (size_t)i*DFF;
        const float* b2v = b2 + (size_t)i*DD;

        // fused QKV projection -> g_qkv fp32 [NTOK,1536]
        bf16_gemm<0,128><<<gQKV, blk, SM128>>>(pxh, pxl, wh + WT_QKV, wl + WT_QKV,
                                    pbqkv + (size_t)i*QSTR, nullptr,
                                    pqkv, nullptr, nullptr, NTOK, QSTR, DD);

        // chunked causal linear attention -> split bf16 att
        attn_kvc_kernel   <<<BH*NC, blk>>>(pqkv, pkvc);
        attn_prefix_kernel<<<BH*16, blk>>>(pkvc, pst);
        attn_out_kernel   <<<BH*NC, blk, ATTN_SMEM>>>(pqkv, pst, path, patl);

        // out proj + residual -> LN1 (LN emits fp32 + split)
        bf16_gemm<2,64><<<gO, blk, SM64>>>(path, patl, wh + WT_O, wl + WT_O,
                                  bov, px, ptmp, nullptr, nullptr, NTOK, DD, DD);
        ln_kernel<<<NTOK, blk>>>(ptmp, g1 + (size_t)i*DD, be1 + (size_t)i*DD, px, pxh, pxl);

        // FFN
        bf16_gemm<1,128><<<gDF, blk, SM128>>>(pxh, pxl, wh + WT_1, wl + WT_1,
                                   b1v, nullptr, nullptr, pffh, pffl, NTOK, DFF, DD);
        bf16_gemm<2,64><<<gO, blk, SM64>>>(pffh, pffl, wh + WT_2, wl + WT_2,
                                  b2v, px, ptmp, nullptr, nullptr, NTOK, DD, DFF);
        ln_kernel<<<NTOK, blk>>>(ptmp, g2 + (size_t)i*DD, be2 + (size_t)i*DD, px, pxh, pxl);
    }

    // final encoder LayerNorm -> output
    ln_kernel<<<NTOK, blk>>>(px, gf, bef, out, nullptr, nullptr);
}

// round 8
// speedup vs baseline: 1.5283x; 1.5283x over previous
#include <cuda_runtime.h>
#include <cuda_bf16.h>
#include <cstdint>
#include <cstddef>

#define BB   2
#define SS   1024
#define LL   2
#define HH   8
#define DD   512
#define DFF  2048
#define DKH  64
#define NTOK (BB*SS)      // 2048
#define NC   (SS/64)      // 16
#define BH   (BB*HH)      // 16
#define QSTR 1536
#define EPSF 1e-5f

typedef __nv_bfloat16 bf16;

// ---------------- scratch (device globals; no allocation) ----------------
__device__ __align__(128) float g_x   [NTOK*DD];
__device__ __align__(128) float g_tmp [NTOK*DD];
__device__ __align__(128) float g_qkv [NTOK*QSTR];
__device__ __align__(128) float g_kvc [BH*NC*DKH*DKH];
__device__ __align__(128) float g_st  [BH*NC*DKH*DKH];
__device__ __align__(128) bf16  g_xh  [NTOK*DD];
__device__ __align__(128) bf16  g_xl  [NTOK*DD];
__device__ __align__(128) bf16  g_atth[NTOK*DD];
__device__ __align__(128) bf16  g_attl[NTOK*DD];
__device__ __align__(128) bf16  g_ffh [NTOK*DFF];
__device__ __align__(128) bf16  g_ffl [NTOK*DFF];
#define WT_QKV 0
#define WT_O   (QSTR*DD)
#define WT_1   (WT_O + DD*DD)
#define WT_2   (WT_1 + DFF*DD)
#define WT_LAYER (WT_2 + DD*DFF)
__device__ __align__(128) bf16  g_wth [LL*WT_LAYER];
__device__ __align__(128) bf16  g_wtl [LL*WT_LAYER];
__device__ __align__(128) float g_bqkv[LL*QSTR];

// ============================ helpers ==================================
__device__ __forceinline__ void split_bf16(float v, bf16& h, bf16& l){
    h = __float2bfloat16(v);
    l = __float2bfloat16(v - __bfloat162float(h));
}
__device__ __forceinline__ uint32_t smem_u32(const void* p){
    uint32_t r;
    asm("{ .reg .u64 t; cvta.to.shared.u64 t, %1; cvt.u32.u64 %0, t; }" : "=r"(r) : "l"(p));
    return r;
}
__device__ __forceinline__ void mma_bf16(float* d, const uint32_t* a, const uint32_t* b){
    asm volatile(
        "mma.sync.aligned.m16n8k16.row.col.f32.bf16.bf16.f32 "
        "{%0,%1,%2,%3}, {%4,%5,%6,%7}, {%8,%9}, {%0,%1,%2,%3};\n"
        : "+f"(d[0]), "+f"(d[1]), "+f"(d[2]), "+f"(d[3])
        : "r"(a[0]), "r"(a[1]), "r"(a[2]), "r"(a[3]), "r"(b[0]), "r"(b[1]));
}
__device__ __forceinline__ void ldm4(uint32_t* r, uint32_t a){
    asm volatile("ldmatrix.sync.aligned.m8n8.x4.shared.b16 {%0,%1,%2,%3}, [%4];"
        : "=r"(r[0]), "=r"(r[1]), "=r"(r[2]), "=r"(r[3]) : "r"(a));
}
__device__ __forceinline__ void cp16(uint32_t dst, const void* src){
    asm volatile("cp.async.cg.shared.global [%0], [%1], 16;" :: "r"(dst), "l"(src));
}
#define CP_COMMIT() asm volatile("cp.async.commit_group;" ::: "memory")
#define CP_WAIT2()  asm volatile("cp.async.wait_group 2;" ::: "memory")

// ============== bf16 3-term GEMM: C[M,N] = A[M,K] @ B^T ====================
// A?,B?: bf16 [rows,K] row-major (hi/lo split). D = AhBh + AlBh + AhBl.
// BM x 128 tiles, K-chunk 32, 8 warps, 4-stage cp.async ring, ldmatrix frags.
// EPI: 0 = +bias -> fp32 C;  1 = +bias,relu -> split bf16;  2 = +bias+R -> fp32 C
template<int EPI, int BM>
__global__ void __launch_bounds__(256, 1)
bf16_gemm(const bf16* __restrict__ Ah, const bf16* __restrict__ Al,
          const bf16* __restrict__ Bh, const bf16* __restrict__ Bl,
          const float* __restrict__ bias, const float* __restrict__ R,
          float* __restrict__ C, bf16* __restrict__ Ch, bf16* __restrict__ Cl,
          int M, int N, int K)
{
    constexpr int MT     = BM / 32;          // warp m-subtiles
    constexpr int ABYTES = BM * 64;          // one A subtile (h or l)
    constexpr int BBYTES = 128 * 64;         // one B subtile
    constexpr int CHUNK  = 2*ABYTES + 2*BBYTES;
    extern __shared__ __align__(16) char dsm[];
    const uint32_t sbase = smem_u32(dsm);

    const int tid = threadIdx.x, lane = tid & 31, wid = tid >> 5;
    const int wm  = (wid >> 2) * (BM / 2), wn = (wid & 3) * 32;
    const int m0  = blockIdx.y * BM, n0 = blockIdx.x * 128;
    const int nch = K >> 5;

    // hoisted fragment offsets (within a stage)
    uint32_t offA[2][MT], offB[2][2];
#pragma unroll
    for (int ks = 0; ks < 2; ++ks){
        const int g = ks * 2 + (lane >> 4);
#pragma unroll
        for (int np = 0; np < 2; ++np){
            const int n = wn + np*16 + (lane & 15);
            offB[ks][np] = 2*ABYTES + n*64 + ((g ^ ((n >> 1) & 3)) << 4);
        }
#pragma unroll
        for (int mt = 0; mt < MT; ++mt){
            const int r = wm + mt*16 + (lane & 15);
            offA[ks][mt] = r*64 + ((g ^ ((r >> 1) & 3)) << 4);
        }
    }

    float acc[MT][4][4] = {};

    auto load_chunk = [&](int ch){
        const uint32_t bb = sbase + (ch & 3) * CHUNK;
        const int koff = ch * 32;
#pragma unroll
        for (int i = 0; i < ABYTES/16/256; ++i){
            const int u = tid + i * 256, row = u >> 2, g = u & 3;
            const uint32_t dst = bb + row*64 + ((g ^ ((row >> 1) & 3)) << 4);
            const size_t so = (size_t)(m0 + row) * K + koff + g * 8;
            cp16(dst,          Ah + so);
            cp16(dst + ABYTES, Al + so);
        }
#pragma unroll
        for (int i = 0; i < 2; ++i){
            const int u = tid + i * 256, row = u >> 2, g = u & 3;
            const uint32_t dst = bb + 2*ABYTES + row*64 + ((g ^ ((row >> 1) & 3)) << 4);
            const size_t so = (size_t)(n0 + row) * K + koff + g * 8;
            cp16(dst,          Bh + so);
            cp16(dst + BBYTES, Bl + so);
        }
    };

    auto compute = [&](int buf){
        const uint32_t bb = sbase + buf * CHUNK;
#pragma unroll
        for (int ks = 0; ks < 2; ++ks){
            uint32_t bh[4][2], bl[4][2];
#pragma unroll
            for (int np = 0; np < 2; ++np){
                uint32_t t[4];
                ldm4(t, bb + offB[ks][np]);
                bh[2*np][0]=t[0]; bh[2*np][1]=t[2]; bh[2*np+1][0]=t[1]; bh[2*np+1][1]=t[3];
                ldm4(t, bb + offB[ks][np] + BBYTES);
                bl[2*np][0]=t[0]; bl[2*np][1]=t[2]; bl[2*np+1][0]=t[1]; bl[2*np+1][1]=t[3];
            }
#pragma unroll
            for (int mt = 0; mt < MT; ++mt){
                uint32_t ah[4], al[4];
                ldm4(ah, bb + offA[ks][mt]);
                ldm4(al, bb + offA[ks][mt] + ABYTES);
#pragma unroll
                for (int nt = 0; nt < 4; ++nt){
                    mma_bf16(acc[mt][nt], ah, bh[nt]);
                    mma_bf16(acc[mt][nt], al, bh[nt]);
                    mma_bf16(acc[mt][nt], ah, bl[nt]);
                }
            }
        }
    };

    load_chunk(0); CP_COMMIT();
    load_chunk(1); CP_COMMIT();
    load_chunk(2); CP_COMMIT();
    for (int ch = 0; ch < nch; ++ch){
        CP_WAIT2();
        __syncthreads();
        compute(ch & 3);
        __syncthreads();
        if (ch + 3 < nch) load_chunk(ch + 3);
        CP_COMMIT();
    }

    // epilogue: direct from accumulator fragments
#pragma unroll
    for (int mt = 0; mt < MT; ++mt){
#pragma unroll
        for (int nt = 0; nt < 4; ++nt){
            const int col = n0 + wn + nt*8 + (lane & 3) * 2;
            const float b0 = bias[col], b1 = bias[col + 1];
#pragma unroll
            for (int hf = 0; hf < 2; ++hf){
                const int row = m0 + wm + mt*16 + (lane >> 2) + hf*8;
                float v0 = acc[mt][nt][hf*2 + 0] + b0;
                float v1 = acc[mt][nt][hf*2 + 1] + b1;
                const size_t o = (size_t)row * N + col;
                if (EPI == 0){
                    *(float2*)&C[o] = make_float2(v0, v1);
                } else if (EPI == 1){
                    v0 = fmaxf(v0, 0.f); v1 = fmaxf(v1, 0.f);
                    bf16 h0, l0, h1, l1;
                    split_bf16(v0, h0, l0); split_bf16(v1, h1, l1);
                    *(__nv_bfloat162*)&Ch[o] = __nv_bfloat162(h0, h1);
                    *(__nv_bfloat162*)&Cl[o] = __nv_bfloat162(l0, l1);
                } else {
                    const float2 rr = *(const float2*)&R[o];
                    *(float2*)&C[o] = make_float2(v0 + rr.x, v1 + rr.y);
                }
            }
        }
    }
}

// ------- batched weight transpose+split: all 6 matrices, both layers -------
__global__ void transpose_split_all(
    const float* __restrict__ Wq, const float* __restrict__ Wk,
    const float* __restrict__ Wv, const float* __restrict__ Wo,
    const float* __restrict__ W1, const float* __restrict__ W2,
    bf16* __restrict__ wth, bf16* __restrict__ wtl)
{
    const int layer = blockIdx.y;
    int t = blockIdx.x;
    const float* S; int K, N; size_t doff;
    if (t < 1024){
        const int m = t >> 8; t &= 255;
        K = DD; N = DD;
        const float* s4[4] = {Wq, Wk, Wv, Wo};
        S = s4[m] + (size_t)layer * DD * DD;
        doff = (size_t)layer * WT_LAYER + (m < 3 ? (size_t)(WT_QKV + m*DD*DD) : (size_t)WT_O);
    } else if (t < 2048){
        t -= 1024; K = DD; N = DFF;
        S = W1 + (size_t)layer * DD * DFF;
        doff = (size_t)layer * WT_LAYER + WT_1;
    } else {
        t -= 2048; K = DFF; N = DD;
        S = W2 + (size_t)layer * DFF * DD;
        doff = (size_t)layer * WT_LAYER + WT_2;
    }
    const int ntx = N / 32;
    const int n0 = (t % ntx) * 32, k0 = (t / ntx) * 32;

    __shared__ float tt[32][33];
    const int x = threadIdx.x, y = threadIdx.y;   // 32 x 8
#pragma unroll
    for (int i = 0; i < 32; i += 8)
        tt[y + i][x] = S[(size_t)(k0 + y + i) * N + n0 + x];
    __syncthreads();
#pragma unroll
    for (int i = 0; i < 32; i += 8){
        const float v = tt[x][y + i];
        bf16 h, l; split_bf16(v, h, l);
        const size_t o = doff + (size_t)(n0 + y + i) * K + k0 + x;
        wth[o] = h; wtl[o] = l;
    }
}

// ---------------- split fp32 -> bf16 hi/lo ---------------------------------
__global__ void split_kernel(const float* __restrict__ X, bf16* __restrict__ Xh,
                             bf16* __restrict__ Xl)
{
    const int t = blockIdx.x * 256 + threadIdx.x;
    const float4 v = ((const float4*)X)[t];
    bf16 h0,l0,h1,l1,h2,l2,h3,l3;
    split_bf16(v.x,h0,l0); split_bf16(v.y,h1,l1);
    split_bf16(v.z,h2,l2); split_bf16(v.w,h3,l3);
    ((__nv_bfloat162*)Xh)[t*2+0] = __nv_bfloat162(h0,h1);
    ((__nv_bfloat162*)Xh)[t*2+1] = __nv_bfloat162(h2,h3);
    ((__nv_bfloat162*)Xl)[t*2+0] = __nv_bfloat162(l0,l1);
    ((__nv_bfloat162*)Xl)[t*2+1] = __nv_bfloat162(l2,l3);
}

__global__ void concat_bias(const float* __restrict__ bq, const float* __restrict__ bk,
                            const float* __restrict__ bv, float* __restrict__ dst)
{
    const int layer = blockIdx.y;
    const int t = blockIdx.x * 256 + threadIdx.x;
    float* d = dst + (size_t)layer * QSTR;
    if (t < 512)       d[t] = bq[layer*DD + t];
    else if (t < 1024) d[t] = bk[layer*DD + t - 512];
    else if (t < 1536) d[t] = bv[layer*DD + t - 1024];
}

// ---------------- LayerNorm (+ optional bf16 split outputs) ----------------
__global__ void ln_kernel(const float* __restrict__ X, const float* __restrict__ g,
                          const float* __restrict__ b, float* __restrict__ Y,
                          bf16* __restrict__ Yh, bf16* __restrict__ Yl)
{
    const int row = blockIdx.x;
    const int tid = threadIdx.x;
    const float* x = X + (size_t)row * DD;
    __shared__ float rs[256], rs2[256];
    float s = 0.f, s2 = 0.f;
    for (int j = tid; j < DD; j += 256) { float v = x[j]; s += v; s2 += v*v; }
    rs[tid] = s; rs2[tid] = s2;
    __syncthreads();
    for (int o = 128; o > 0; o >>= 1) {
        if (tid < o) { rs[tid] += rs[tid+o]; rs2[tid] += rs2[tid+o]; }
        __syncthreads();
    }
    const float m    = rs[0] * (1.f/DD);
    const float var  = rs2[0] * (1.f/DD) - m*m;
    const float rstd = rsqrtf(var + EPSF);
    for (int j = tid; j < DD; j += 256){
        const float v = (x[j] - m) * rstd * g[j] + b[j];
        Y[(size_t)row * DD + j] = v;
        if (Yh){
            bf16 h, l; split_bf16(v, h, l);
            Yh[(size_t)row * DD + j] = h;
            Yl[(size_t)row * DD + j] = l;
        }
    }
}

// ---------------- attention kernel 1: per-chunk K^T V [64x64] --------------
__global__ void attn_kvc_kernel(const float* __restrict__ QKV, float* __restrict__ kvc)
{
    __shared__ float ks[64][68], vs[64][68];
    const int blk = blockIdx.x;
    const int bh  = blk >> 4, c = blk & 15;
    const int b   = bh >> 3,  h = bh & 7;
    const int tid = threadIdx.x;
    const int j   = tid >> 2, base = (tid & 3) * 16;

    const size_t tok = (size_t)(b*SS + c*64 + j) * QSTR + h*DKH + base;
    const float* Kx = QKV + DD;
    const float* Vx = QKV + 2*DD;
#pragma unroll
    for (int u = 0; u < 4; ++u) {
        *(float4*)&ks[j][base + u*4] = *(const float4*)&Kx[tok + u*4];
        *(float4*)&vs[j][base + u*4] = *(const float4*)&Vx[tok + u*4];
    }
    __syncthreads();

    const int p = tid >> 2, qb = tid & 3;
    float acc[16] = {};
    for (int jj = 0; jj < 64; ++jj) {
        const float kp = ks[jj][p];
#pragma unroll
        for (int i = 0; i < 16; ++i) acc[i] += kp * vs[jj][qb + 4*i];
    }
    float* out = kvc + (size_t)blk * 4096 + p * 64;
#pragma unroll
    for (int i = 0; i < 16; ++i) out[qb + 4*i] = acc[i];
}

// ---------------- attention kernel 2: exclusive prefix over chunks ---------
__global__ void attn_prefix_kernel(const float* __restrict__ kvc, float* __restrict__ st)
{
    const int bh = blockIdx.x >> 4, r = blockIdx.x & 15;
    const int e  = threadIdx.x + r * 256;
    const size_t base = (size_t)bh * NC * 4096 + e;
    float v[NC];
#pragma unroll
    for (int c = 0; c < NC; ++c) v[c] = kvc[base + (size_t)c * 4096];
    float run = 0.f;
#pragma unroll
    for (int c = 0; c < NC; ++c) { st[base + (size_t)c * 4096] = run; run += v[c]; }
}

// ---------------- attention kernel 3: O = tril(QK^T)V + Q*state ------------
__global__ void attn_out_kernel(const float* __restrict__ QKV, const float* __restrict__ st,
                                bf16* __restrict__ Ath, bf16* __restrict__ Atl)
{
    extern __shared__ float sm[];
    float (*qs )[68] = (float(*)[68])sm;
    float (*ks )[68] = qs  + 64;
    float (*vs )[68] = ks  + 64;
    float (*ssm)[68] = vs  + 64;
    float (*sts)[68] = ssm + 64;

    const int blk = blockIdx.x;
    const int bh  = blk >> 4, c = blk & 15;
    const int b   = bh >> 3,  h = bh & 7;
    const int tid = threadIdx.x;
    const int row = tid >> 2, base = (tid & 3) * 16;

    const size_t tok = (size_t)(b*SS + c*64 + row) * QSTR + h*DKH + base;
    const float* stg = st + (size_t)blk * 4096 + row * 64 + base;
#pragma unroll
    for (int u = 0; u < 4; ++u) {
        *(float4*)&qs [row][base + u*4] = *(const float4*)&QKV[tok + u*4];
        *(float4*)&ks [row][base + u*4] = *(const float4*)&QKV[tok + DD + u*4];
        *(float4*)&vs [row][base + u*4] = *(const float4*)&QKV[tok + 2*DD + u*4];
        *(float4*)&sts[row][base + u*4] = *(const float4*)&stg[u*4];
    }
    __syncthreads();

    const int i = tid >> 2, j0 = tid & 3;
    for (int jj = 0; jj < 16; ++jj) {
        const int j = j0 + 4*jj;
        float d = 0.f;
#pragma unroll
        for (int p = 0; p < 64; ++p) d += qs[i][p] * ks[j][p];
        ssm[i][j] = (j <= i) ? d : 0.f;
    }
    __syncthreads();

    float acc[16] = {};
    for (int jj = 0; jj < 64; ++jj) {
        const float sij = ssm[i][jj];
        const float qip = qs[i][jj];
#pragma unroll
        for (int dd = 0; dd < 16; ++dd) {
            acc[dd] += sij * vs[jj][j0 + 4*dd];
            acc[dd] += qip * sts[jj][j0 + 4*dd];
        }
    }
    const size_t outp = (size_t)(b*SS + c*64 + i) * DD + h*DKH;
#pragma unroll
    for (int dd = 0; dd < 16; ++dd){
        bf16 h2, l2; split_bf16(acc[dd], h2, l2);
        Ath[outp + j0 + 4*dd] = h2;
        Atl[outp + j0 + 4*dd] = l2;
    }
}

// ---------------------------------------------------------------------------
extern "C" void kernel_launch(void* const* d_in, const int* in_sizes, int n_in,
                              void* d_out, int out_size)
{
    const float* src = (const float*)d_in[0];
    const float* Wq  = (const float*)d_in[1];
    const float* bq  = (const float*)d_in[2];
    const float* Wk  = (const float*)d_in[3];
    const float* bk  = (const float*)d_in[4];
    const float* Wv  = (const float*)d_in[5];
    const float* bv  = (const float*)d_in[6];
    const float* Wo  = (const float*)d_in[7];
    const float* bo  = (const float*)d_in[8];
    const float* W1  = (const float*)d_in[9];
    const float* b1  = (const float*)d_in[10];
    const float* W2  = (const float*)d_in[11];
    const float* b2  = (const float*)d_in[12];
    const float* g1  = (const float*)d_in[13];
    const float* be1 = (const float*)d_in[14];
    const float* g2  = (const float*)d_in[15];
    const float* be2 = (const float*)d_in[16];
    const float* gf  = (const float*)d_in[17];
    const float* bef = (const float*)d_in[18];
    float* out = (float*)d_out;

    float *px, *ptmp, *pqkv, *pkvc, *pst, *pbqkv;
    bf16 *pxh, *pxl, *path, *patl, *pffh, *pffl, *pwth, *pwtl;
    cudaGetSymbolAddress((void**)&px,    g_x);
    cudaGetSymbolAddress((void**)&ptmp,  g_tmp);
    cudaGetSymbolAddress((void**)&pqkv,  g_qkv);
    cudaGetSymbolAddress((void**)&pkvc,  g_kvc);
    cudaGetSymbolAddress((void**)&pst,   g_st);
    cudaGetSymbolAddress((void**)&pbqkv, g_bqkv);
    cudaGetSymbolAddress((void**)&pxh,   g_xh);
    cudaGetSymbolAddress((void**)&pxl,   g_xl);
    cudaGetSymbolAddress((void**)&path,  g_atth);
    cudaGetSymbolAddress((void**)&patl,  g_attl);
    cudaGetSymbolAddress((void**)&pffh,  g_ffh);
    cudaGetSymbolAddress((void**)&pffl,  g_ffl);
    cudaGetSymbolAddress((void**)&pwth,  g_wth);
    cudaGetSymbolAddress((void**)&pwtl,  g_wtl);

    static const int ATTN_SMEM = 5 * 64 * 68 * 4;        // 87,040 B
    static const int SM128 = 4 * (2*128*64 + 2*128*64);  // 131,072 B
    static const int SM64  = 4 * (2*64*64  + 2*128*64);  // 98,304 B
    cudaFuncSetAttribute(attn_out_kernel, cudaFuncAttributeMaxDynamicSharedMemorySize, ATTN_SMEM);
    cudaFuncSetAttribute(bf16_gemm<0,128>, cudaFuncAttributeMaxDynamicSharedMemorySize, SM128);
    cudaFuncSetAttribute(bf16_gemm<1,128>, cudaFuncAttributeMaxDynamicSharedMemorySize, SM128);
    cudaFuncSetAttribute(bf16_gemm<2,64>,  cudaFuncAttributeMaxDynamicSharedMemorySize, SM64);

    // x = src (residual); split src for QKV GEMM
    cudaMemcpyAsync(px, src, (size_t)NTOK * DD * sizeof(float), cudaMemcpyDeviceToDevice, 0);
    split_kernel<<<NTOK*DD/4/256, 256>>>(src, pxh, pxl);

    // weight prep: single batched kernel + bias concat
    transpose_split_all<<<dim3(3072, LL), dim3(32, 8)>>>(Wq, Wk, Wv, Wo, W1, W2, pwth, pwtl);
    concat_bias<<<dim3(6, LL), 256>>>(bq, bk, bv, pbqkv);

    const dim3 gQKV(QSTR / 128, NTOK / 128);   // 12 x 16
    const dim3 gO  (DD   / 128, NTOK / 64);    // 4 x 32  (BM=64)
    const dim3 gDF (DFF  / 128, NTOK / 128);   // 16 x 16
    const dim3 blk(256);

    for (int i = 0; i < LL; ++i) {
        bf16* wh = pwth + (size_t)i * WT_LAYER;
        bf16* wl = pwtl + (size_t)i * WT_LAYER;
        const float* bov = bo + (size_t)i*DD;
        const float* b1v = b1 + (size_t)i*DFF;
        const float* b2v = b2 + (size_t)i*DD;

        // fused QKV projection -> g_qkv fp32 [NTOK,1536]
        bf16_gemm<0,128><<<gQKV, blk, SM128>>>(pxh, pxl, wh + WT_QKV, wl + WT_QKV,
                                    pbqkv + (size_t)i*QSTR, nullptr,
                                    pqkv, nullptr, nullptr, NTOK, QSTR, DD);

        // chunked causal linear attention -> split bf16 att
        attn_kvc_kernel   <<<BH*NC, blk>>>(pqkv, pkvc);
        attn_prefix_kernel<<<BH*16, blk>>>(pkvc, pst);
        attn_out_kernel   <<<BH*NC, blk, ATTN_SMEM>>>(pqkv, pst, path, patl);

        // out proj + residual -> LN1 (LN emits fp32 + split)
        bf16_gemm<2,64><<<gO, blk, SM64>>>(path, patl, wh + WT_O, wl + WT_O,
                                  bov, px, ptmp, nullptr, nullptr, NTOK, DD, DD);
        ln_kernel<<<NTOK, blk>>>(ptmp, g1 + (size_t)i*DD, be1 + (size_t)i*DD, px, pxh, pxl);

        // FFN
        bf16_gemm<1,128><<<gDF, blk, SM128>>>(pxh, pxl, wh + WT_1, wl + WT_1,
                                   b1v, nullptr, nullptr, pffh, pffl, NTOK, DFF, DD);
        bf16_gemm<2,64><<<gO, blk, SM64>>>(pffh, pffl, wh + WT_2, wl + WT_2,
                                  b2v, px, ptmp, nullptr, nullptr, NTOK, DD, DFF);
        ln_kernel<<<NTOK, blk>>>(ptmp, g2 + (size_t)i*DD, be2 + (size_t)i*DD, px, pxh, pxl);
    }

    // final encoder LayerNorm -> output
    ln_kernel<<<NTOK, blk>>>(px, gf, bef, out, nullptr, nullptr);
}

// round 9
// speedup vs baseline: 1.6088x; 1.0527x over previous
#include <cuda_runtime.h>
#include <cuda_bf16.h>
#include <cstdint>
#include <cstddef>

#define BB   2
#define SS   1024
#define LL   2
#define HH   8
#define DD   512
#define DFF  2048
#define DKH  64
#define NTOK (BB*SS)      // 2048
#define NC   (SS/64)      // 16
#define BH   (BB*HH)      // 16
#define QSTR 1536
#define EPSF 1e-5f

typedef __nv_bfloat16 bf16;

// ---------------- scratch (device globals; no allocation) ----------------
__device__ __align__(128) float g_x   [NTOK*DD];
__device__ __align__(128) float g_tmp [NTOK*DD];
__device__ __align__(128) float g_qkv [NTOK*QSTR];
__device__ __align__(128) float g_kvc [BH*NC*DKH*DKH];
__device__ __align__(128) float g_st  [BH*NC*DKH*DKH];
__device__ __align__(128) bf16  g_xh  [NTOK*DD];
__device__ __align__(128) bf16  g_xl  [NTOK*DD];
__device__ __align__(128) bf16  g_atth[NTOK*DD];
__device__ __align__(128) bf16  g_attl[NTOK*DD];
__device__ __align__(128) bf16  g_ffh [NTOK*DFF];
__device__ __align__(128) bf16  g_ffl [NTOK*DFF];
#define WT_QKV 0
#define WT_O   (QSTR*DD)
#define WT_1   (WT_O + DD*DD)
#define WT_2   (WT_1 + DFF*DD)
#define WT_LAYER (WT_2 + DD*DFF)
__device__ __align__(128) bf16  g_wth [LL*WT_LAYER];
__device__ __align__(128) bf16  g_wtl [LL*WT_LAYER];
__device__ __align__(128) float g_bqkv[LL*QSTR];

// ============================ helpers ==================================
__device__ __forceinline__ void split_bf16(float v, bf16& h, bf16& l){
    h = __float2bfloat16(v);
    l = __float2bfloat16(v - __bfloat162float(h));
}
__device__ __forceinline__ uint32_t smem_u32(const void* p){
    uint32_t r;
    asm("{ .reg .u64 t; cvta.to.shared.u64 t, %1; cvt.u32.u64 %0, t; }" : "=r"(r) : "l"(p));
    return r;
}
__device__ __forceinline__ void mma_bf16(float* d, const uint32_t* a, const uint32_t* b){
    asm volatile(
        "mma.sync.aligned.m16n8k16.row.col.f32.bf16.bf16.f32 "
        "{%0,%1,%2,%3}, {%4,%5,%6,%7}, {%8,%9}, {%0,%1,%2,%3};\n"
        : "+f"(d[0]), "+f"(d[1]), "+f"(d[2]), "+f"(d[3])
        : "r"(a[0]), "r"(a[1]), "r"(a[2]), "r"(a[3]), "r"(b[0]), "r"(b[1]));
}
__device__ __forceinline__ void ldm4(uint32_t* r, uint32_t a){
    asm volatile("ldmatrix.sync.aligned.m8n8.x4.shared.b16 {%0,%1,%2,%3}, [%4];"
        : "=r"(r[0]), "=r"(r[1]), "=r"(r[2]), "=r"(r[3]) : "r"(a));
}
__device__ __forceinline__ void cp16(uint32_t dst, const void* src){
    asm volatile("cp.async.cg.shared.global [%0], [%1], 16;" :: "r"(dst), "l"(src));
}
#define CP_COMMIT() asm volatile("cp.async.commit_group;" ::: "memory")
#define CP_WAIT1()  asm volatile("cp.async.wait_group 1;" ::: "memory")

// ============== bf16 3-term GEMM: C[M,N] = A[M,K] @ B^T ====================
// A?,B?: bf16 [rows,K] row-major (hi/lo split). D = AhBh + AlBh + AhBl.
// BM x 128 tiles, K-chunk 32, 8 warps, 3-stage cp.async ring, ldmatrix frags,
// 2 CTAs/SM.  EPI: 0=+bias->fp32; 1=+bias,relu->split bf16; 2=+bias+R->fp32
template<int EPI, int BM>
__global__ void __launch_bounds__(256, 2)
bf16_gemm(const bf16* __restrict__ Ah, const bf16* __restrict__ Al,
          const bf16* __restrict__ Bh, const bf16* __restrict__ Bl,
          const float* __restrict__ bias, const float* __restrict__ R,
          float* __restrict__ C, bf16* __restrict__ Ch, bf16* __restrict__ Cl,
          int M, int N, int K)
{
    constexpr int MT     = BM / 32;          // warp m-subtiles
    constexpr int ABYTES = BM * 64;          // one A subtile (h or l)
    constexpr int BBYTES = 128 * 64;         // one B subtile
    constexpr int CHUNK  = 2*ABYTES + 2*BBYTES;
    extern __shared__ __align__(16) char dsm[];
    const uint32_t sbase = smem_u32(dsm);

    const int tid = threadIdx.x, lane = tid & 31, wid = tid >> 5;
    const int wm  = (wid >> 2) * (BM / 2), wn = (wid & 3) * 32;
    const int m0  = blockIdx.y * BM, n0 = blockIdx.x * 128;
    const int nch = K >> 5;

    // hoisted fragment offsets (within a stage)
    uint32_t offA[2][MT], offB[2][2];
#pragma unroll
    for (int ks = 0; ks < 2; ++ks){
        const int g = ks * 2 + (lane >> 4);
#pragma unroll
        for (int np = 0; np < 2; ++np){
            const int n = wn + np*16 + (lane & 15);
            offB[ks][np] = 2*ABYTES + n*64 + ((g ^ ((n >> 1) & 3)) << 4);
        }
#pragma unroll
        for (int mt = 0; mt < MT; ++mt){
            const int r = wm + mt*16 + (lane & 15);
            offA[ks][mt] = r*64 + ((g ^ ((r >> 1) & 3)) << 4);
        }
    }

    float acc[MT][4][4] = {};

    auto load_chunk = [&](int stage, int ch){
        const uint32_t bb = sbase + stage * CHUNK;
        const int koff = ch * 32;
#pragma unroll
        for (int i = 0; i < ABYTES/16/256; ++i){
            const int u = tid + i * 256, row = u >> 2, g = u & 3;
            const uint32_t dst = bb + row*64 + ((g ^ ((row >> 1) & 3)) << 4);
            const size_t so = (size_t)(m0 + row) * K + koff + g * 8;
            cp16(dst,          Ah + so);
            cp16(dst + ABYTES, Al + so);
        }
#pragma unroll
        for (int i = 0; i < 2; ++i){
            const int u = tid + i * 256, row = u >> 2, g = u & 3;
            const uint32_t dst = bb + 2*ABYTES + row*64 + ((g ^ ((row >> 1) & 3)) << 4);
            const size_t so = (size_t)(n0 + row) * K + koff + g * 8;
            cp16(dst,          Bh + so);
            cp16(dst + BBYTES, Bl + so);
        }
    };

    auto compute = [&](int stage){
        const uint32_t bb = sbase + stage * CHUNK;
#pragma unroll
        for (int ks = 0; ks < 2; ++ks){
            uint32_t bh[4][2], bl[4][2];
#pragma unroll
            for (int np = 0; np < 2; ++np){
                uint32_t t[4];
                ldm4(t, bb + offB[ks][np]);
                bh[2*np][0]=t[0]; bh[2*np][1]=t[2]; bh[2*np+1][0]=t[1]; bh[2*np+1][1]=t[3];
                ldm4(t, bb + offB[ks][np] + BBYTES);
                bl[2*np][0]=t[0]; bl[2*np][1]=t[2]; bl[2*np+1][0]=t[1]; bl[2*np+1][1]=t[3];
            }
#pragma unroll
            for (int mt = 0; mt < MT; ++mt){
                uint32_t ah[4], al[4];
                ldm4(ah, bb + offA[ks][mt]);
                ldm4(al, bb + offA[ks][mt] + ABYTES);
#pragma unroll
                for (int nt = 0; nt < 4; ++nt){
                    mma_bf16(acc[mt][nt], ah, bh[nt]);
                    mma_bf16(acc[mt][nt], al, bh[nt]);
                    mma_bf16(acc[mt][nt], ah, bl[nt]);
                }
            }
        }
    };

    load_chunk(0, 0); CP_COMMIT();
    load_chunk(1, 1); CP_COMMIT();
    int cst = 0, lst = 2;
    for (int ch = 0; ch < nch; ++ch){
        CP_WAIT1();
        __syncthreads();
        if (ch + 2 < nch) load_chunk(lst, ch + 2);
        CP_COMMIT();
        compute(cst);
        cst = (cst == 2) ? 0 : cst + 1;
        lst = (lst == 2) ? 0 : lst + 1;
    }

    // epilogue: direct from accumulator fragments
#pragma unroll
    for (int mt = 0; mt < MT; ++mt){
#pragma unroll
        for (int nt = 0; nt < 4; ++nt){
            const int col = n0 + wn + nt*8 + (lane & 3) * 2;
            const float b0 = bias[col], b1 = bias[col + 1];
#pragma unroll
            for (int hf = 0; hf < 2; ++hf){
                const int row = m0 + wm + mt*16 + (lane >> 2) + hf*8;
                float v0 = acc[mt][nt][hf*2 + 0] + b0;
                float v1 = acc[mt][nt][hf*2 + 1] + b1;
                const size_t o = (size_t)row * N + col;
                if (EPI == 0){
                    *(float2*)&C[o] = make_float2(v0, v1);
                } else if (EPI == 1){
                    v0 = fmaxf(v0, 0.f); v1 = fmaxf(v1, 0.f);
                    bf16 h0, l0, h1, l1;
                    split_bf16(v0, h0, l0); split_bf16(v1, h1, l1);
                    *(__nv_bfloat162*)&Ch[o] = __nv_bfloat162(h0, h1);
                    *(__nv_bfloat162*)&Cl[o] = __nv_bfloat162(l0, l1);
                } else {
                    const float2 rr = *(const float2*)&R[o];
                    *(float2*)&C[o] = make_float2(v0 + rr.x, v1 + rr.y);
                }
            }
        }
    }
}

// ------- batched weight transpose+split: all 6 matrices, both layers -------
__global__ void transpose_split_all(
    const float* __restrict__ Wq, const float* __restrict__ Wk,
    const float* __restrict__ Wv, const float* __restrict__ Wo,
    const float* __restrict__ W1, const float* __restrict__ W2,
    bf16* __restrict__ wth, bf16* __restrict__ wtl)
{
    const int layer = blockIdx.y;
    int t = blockIdx.x;
    const float* S; int K, N; size_t doff;
    if (t < 1024){
        const int m = t >> 8; t &= 255;
        K = DD; N = DD;
        const float* s4[4] = {Wq, Wk, Wv, Wo};
        S = s4[m] + (size_t)layer * DD * DD;
        doff = (size_t)layer * WT_LAYER + (m < 3 ? (size_t)(WT_QKV + m*DD*DD) : (size_t)WT_O);
    } else if (t < 2048){
        t -= 1024; K = DD; N = DFF;
        S = W1 + (size_t)layer * DD * DFF;
        doff = (size_t)layer * WT_LAYER + WT_1;
    } else {
        t -= 2048; K = DFF; N = DD;
        S = W2 + (size_t)layer * DFF * DD;
        doff = (size_t)layer * WT_LAYER + WT_2;
    }
    const int ntx = N / 32;
    const int n0 = (t % ntx) * 32, k0 = (t / ntx) * 32;

    __shared__ float tt[32][33];
    const int x = threadIdx.x, y = threadIdx.y;   // 32 x 8
#pragma unroll
    for (int i = 0; i < 32; i += 8)
        tt[y + i][x] = S[(size_t)(k0 + y + i) * N + n0 + x];
    __syncthreads();
#pragma unroll
    for (int i = 0; i < 32; i += 8){
        const float v = tt[x][y + i];
        bf16 h, l; split_bf16(v, h, l);
        const size_t o = doff + (size_t)(n0 + y + i) * K + k0 + x;
        wth[o] = h; wtl[o] = l;
    }
}

// ---------------- split fp32 -> bf16 hi/lo ---------------------------------
__global__ void split_kernel(const float* __restrict__ X, bf16* __restrict__ Xh,
                             bf16* __restrict__ Xl)
{
    const int t = blockIdx.x * 256 + threadIdx.x;
    const float4 v = ((const float4*)X)[t];
    bf16 h0,l0,h1,l1,h2,l2,h3,l3;
    split_bf16(v.x,h0,l0); split_bf16(v.y,h1,l1);
    split_bf16(v.z,h2,l2); split_bf16(v.w,h3,l3);
    ((__nv_bfloat162*)Xh)[t*2+0] = __nv_bfloat162(h0,h1);
    ((__nv_bfloat162*)Xh)[t*2+1] = __nv_bfloat162(h2,h3);
    ((__nv_bfloat162*)Xl)[t*2+0] = __nv_bfloat162(l0,l1);
    ((__nv_bfloat162*)Xl)[t*2+1] = __nv_bfloat162(l2,l3);
}

__global__ void concat_bias(const float* __restrict__ bq, const float* __restrict__ bk,
                            const float* __restrict__ bv, float* __restrict__ dst)
{
    const int layer = blockIdx.y;
    const int t = blockIdx.x * 256 + threadIdx.x;
    float* d = dst + (size_t)layer * QSTR;
    if (t < 512)       d[t] = bq[layer*DD + t];
    else if (t < 1024) d[t] = bk[layer*DD + t - 512];
    else if (t < 1536) d[t] = bv[layer*DD + t - 1024];
}

// ---------------- LayerNorm (+ optional bf16 split outputs) ----------------
__global__ void ln_kernel(const float* __restrict__ X, const float* __restrict__ g,
                          const float* __restrict__ b, float* __restrict__ Y,
                          bf16* __restrict__ Yh, bf16* __restrict__ Yl)
{
    const int row = blockIdx.x;
    const int tid = threadIdx.x;
    const float* x = X + (size_t)row * DD;
    __shared__ float rs[256], rs2[256];
    float s = 0.f, s2 = 0.f;
    for (int j = tid; j < DD; j += 256) { float v = x[j]; s += v; s2 += v*v; }
    rs[tid] = s; rs2[tid] = s2;
    __syncthreads();
    for (int o = 128; o > 0; o >>= 1) {
        if (tid < o) { rs[tid] += rs[tid+o]; rs2[tid] += rs2[tid+o]; }
        __syncthreads();
    }
    const float m    = rs[0] * (1.f/DD);
    const float var  = rs2[0] * (1.f/DD) - m*m;
    const float rstd = rsqrtf(var + EPSF);
    for (int j = tid; j < DD; j += 256){
        const float v = (x[j] - m) * rstd * g[j] + b[j];
        Y[(size_t)row * DD + j] = v;
        if (Yh){
            bf16 h, l; split_bf16(v, h, l);
            Yh[(size_t)row * DD + j] = h;
            Yl[(size_t)row * DD + j] = l;
        }
    }
}

// ---------------- attention kernel 1: per-chunk K^T V [64x64] --------------
__global__ void attn_kvc_kernel(const float* __restrict__ QKV, float* __restrict__ kvc)
{
    __shared__ float ks[64][68], vs[64][68];
    const int blk = blockIdx.x;
    const int bh  = blk >> 4, c = blk & 15;
    const int b   = bh >> 3,  h = bh & 7;
    const int tid = threadIdx.x;
    const int j   = tid >> 2, base = (tid & 3) * 16;

    const size_t tok = (size_t)(b*SS + c*64 + j) * QSTR + h*DKH + base;
    const float* Kx = QKV + DD;
    const float* Vx = QKV + 2*DD;
#pragma unroll
    for (int u = 0; u < 4; ++u) {
        *(float4*)&ks[j][base + u*4] = *(const float4*)&Kx[tok + u*4];
        *(float4*)&vs[j][base + u*4] = *(const float4*)&Vx[tok + u*4];
    }
    __syncthreads();

    const int p = tid >> 2, qb = tid & 3;
    float acc[16] = {};
    for (int jj = 0; jj < 64; ++jj) {
        const float kp = ks[jj][p];
#pragma unroll
        for (int i = 0; i < 16; ++i) acc[i] += kp * vs[jj][qb + 4*i];
    }
    float* out = kvc + (size_t)blk * 4096 + p * 64;
#pragma unroll
    for (int i = 0; i < 16; ++i) out[qb + 4*i] = acc[i];
}

// ---------------- attention kernel 2: exclusive prefix over chunks ---------
__global__ void attn_prefix_kernel(const float* __restrict__ kvc, float* __restrict__ st)
{
    const int bh = blockIdx.x >> 4, r = blockIdx.x & 15;
    const int e  = threadIdx.x + r * 256;
    const size_t base = (size_t)bh * NC * 4096 + e;
    float v[NC];
#pragma unroll
    for (int c = 0; c < NC; ++c) v[c] = kvc[base + (size_t)c * 4096];
    float run = 0.f;
#pragma unroll
    for (int c = 0; c < NC; ++c) { st[base + (size_t)c * 4096] = run; run += v[c]; }
}

// ---------------- attention kernel 3: O = tril(QK^T)V + Q*state ------------
__global__ void attn_out_kernel(const float* __restrict__ QKV, const float* __restrict__ st,
                                bf16* __restrict__ Ath, bf16* __restrict__ Atl)
{
    extern __shared__ float sm[];
    float (*qs )[68] = (float(*)[68])sm;
    float (*ks )[68] = qs  + 64;
    float (*vs )[68] = ks  + 64;
    float (*ssm)[68] = vs  + 64;
    float (*sts)[68] = ssm + 64;

    const int blk = blockIdx.x;
    const int bh  = blk >> 4, c = blk & 15;
    const int b   = bh >> 3,  h = bh & 7;
    const int tid = threadIdx.x;
    const int row = tid >> 2, base = (tid & 3) * 16;

    const size_t tok = (size_t)(b*SS + c*64 + row) * QSTR + h*DKH + base;
    const float* stg = st + (size_t)blk * 4096 + row * 64 + base;
#pragma unroll
    for (int u = 0; u < 4; ++u) {
        *(float4*)&qs [row][base + u*4] = *(const float4*)&QKV[tok + u*4];
        *(float4*)&ks [row][base + u*4] = *(const float4*)&QKV[tok + DD + u*4];
        *(float4*)&vs [row][base + u*4] = *(const float4*)&QKV[tok + 2*DD + u*4];
        *(float4*)&sts[row][base + u*4] = *(const float4*)&stg[u*4];
    }
    __syncthreads();

    const int i = tid >> 2, j0 = tid & 3;
    for (int jj = 0; jj < 16; ++jj) {
        const int j = j0 + 4*jj;
        float d = 0.f;
#pragma unroll
        for (int p = 0; p < 64; ++p) d += qs[i][p] * ks[j][p];
        ssm[i][j] = (j <= i) ? d : 0.f;
    }
    __syncthreads();

    float acc[16] = {};
    for (int jj = 0; jj < 64; ++jj) {
        const float sij = ssm[i][jj];
        const float qip = qs[i][jj];
#pragma unroll
        for (int dd = 0; dd < 16; ++dd) {
            acc[dd] += sij * vs[jj][j0 + 4*dd];
            acc[dd] += qip * sts[jj][j0 + 4*dd];
        }
    }
    const size_t outp = (size_t)(b*SS + c*64 + i) * DD + h*DKH;
#pragma unroll
    for (int dd = 0; dd < 16; ++dd){
        bf16 h2, l2; split_bf16(acc[dd], h2, l2);
        Ath[outp + j0 + 4*dd] = h2;
        Atl[outp + j0 + 4*dd] = l2;
    }
}

// ---------------------------------------------------------------------------
extern "C" void kernel_launch(void* const* d_in, const int* in_sizes, int n_in,
                              void* d_out, int out_size)
{
    const float* src = (const float*)d_in[0];
    const float* Wq  = (const float*)d_in[1];
    const float* bq  = (const float*)d_in[2];
    const float* Wk  = (const float*)d_in[3];
    const float* bk  = (const float*)d_in[4];
    const float* Wv  = (const float*)d_in[5];
    const float* bv  = (const float*)d_in[6];
    const float* Wo  = (const float*)d_in[7];
    const float* bo  = (const float*)d_in[8];
    const float* W1  = (const float*)d_in[9];
    const float* b1  = (const float*)d_in[10];
    const float* W2  = (const float*)d_in[11];
    const float* b2  = (const float*)d_in[12];
    const float* g1  = (const float*)d_in[13];
    const float* be1 = (const float*)d_in[14];
    const float* g2  = (const float*)d_in[15];
    const float* be2 = (const float*)d_in[16];
    const float* gf  = (const float*)d_in[17];
    const float* bef = (const float*)d_in[18];
    float* out = (float*)d_out;

    float *px, *ptmp, *pqkv, *pkvc, *pst, *pbqkv;
    bf16 *pxh, *pxl, *path, *patl, *pffh, *pffl, *pwth, *pwtl;
    cudaGetSymbolAddress((void**)&px,    g_x);
    cudaGetSymbolAddress((void**)&ptmp,  g_tmp);
    cudaGetSymbolAddress((void**)&pqkv,  g_qkv);
    cudaGetSymbolAddress((void**)&pkvc,  g_kvc);
    cudaGetSymbolAddress((void**)&pst,   g_st);
    cudaGetSymbolAddress((void**)&pbqkv, g_bqkv);
    cudaGetSymbolAddress((void**)&pxh,   g_xh);
    cudaGetSymbolAddress((void**)&pxl,   g_xl);
    cudaGetSymbolAddress((void**)&path,  g_atth);
    cudaGetSymbolAddress((void**)&patl,  g_attl);
    cudaGetSymbolAddress((void**)&pffh,  g_ffh);
    cudaGetSymbolAddress((void**)&pffl,  g_ffl);
    cudaGetSymbolAddress((void**)&pwth,  g_wth);
    cudaGetSymbolAddress((void**)&pwtl,  g_wtl);

    static const int ATTN_SMEM = 5 * 64 * 68 * 4;        // 87,040 B
    static const int SM128 = 3 * (2*128*64 + 2*128*64);  // 98,304 B
    static const int SM64  = 3 * (2*64*64  + 2*128*64);  // 73,728 B
    cudaFuncSetAttribute(attn_out_kernel, cudaFuncAttributeMaxDynamicSharedMemorySize, ATTN_SMEM);
    cudaFuncSetAttribute(bf16_gemm<0,128>, cudaFuncAttributeMaxDynamicSharedMemorySize, SM128);
    cudaFuncSetAttribute(bf16_gemm<1,128>, cudaFuncAttributeMaxDynamicSharedMemorySize, SM128);
    cudaFuncSetAttribute(bf16_gemm<2,64>,  cudaFuncAttributeMaxDynamicSharedMemorySize, SM64);

    // x = src (residual); split src for QKV GEMM
    cudaMemcpyAsync(px, src, (size_t)NTOK * DD * sizeof(float), cudaMemcpyDeviceToDevice, 0);
    split_kernel<<<NTOK*DD/4/256, 256>>>(src, pxh, pxl);

    // weight prep: single batched kernel + bias concat
    transpose_split_all<<<dim3(3072, LL), dim3(32, 8)>>>(Wq, Wk, Wv, Wo, W1, W2, pwth, pwtl);
    concat_bias<<<dim3(6, LL), 256>>>(bq, bk, bv, pbqkv);

    const dim3 gQKV(QSTR / 128, NTOK / 128);   // 12 x 16
    const dim3 gO  (DD   / 128, NTOK / 64);    // 4 x 32  (BM=64)
    const dim3 gDF (DFF  / 128, NTOK / 128);   // 16 x 16
    const dim3 blk(256);

    for (int i = 0; i < LL; ++i) {
        bf16* wh = pwth + (size_t)i * WT_LAYER;
        bf16* wl = pwtl + (size_t)i * WT_LAYER;
        const float* bov = bo + (size_t)i*DD;
        const float* b1v = b1 + (size_t)i*DFF;
        const float* b2v = b2 + (size_t)i*DD;

        // fused QKV projection -> g_qkv fp32 [NTOK,1536]
        bf16_gemm<0,128><<<gQKV, blk, SM128>>>(pxh, pxl, wh + WT_QKV, wl + WT_QKV,
                                    pbqkv + (size_t)i*QSTR, nullptr,
                                    pqkv, nullptr, nullptr, NTOK, QSTR, DD);

        // chunked causal linear attention -> split bf16 att
        attn_kvc_kernel   <<<BH*NC, blk>>>(pqkv, pkvc);
        attn_prefix_kernel<<<BH*16, blk>>>(pkvc, pst);
        attn_out_kernel   <<<BH*NC, blk, ATTN_SMEM>>>(pqkv, pst, path, patl);

        // out proj + residual -> LN1 (LN emits fp32 + split)
        bf16_gemm<2,64><<<gO, blk, SM64>>>(path, patl, wh + WT_O, wl + WT_O,
                                  bov, px, ptmp, nullptr, nullptr, NTOK, DD, DD);
        ln_kernel<<<NTOK, blk>>>(ptmp, g1 + (size_t)i*DD, be1 + (size_t)i*DD, px, pxh, pxl);

        // FFN
        bf16_gemm<1,128><<<gDF, blk, SM128>>>(pxh, pxl, wh + WT_1, wl + WT_1,
                                   b1v, nullptr, nullptr, pffh, pffl, NTOK, DFF, DD);
        bf16_gemm<2,64><<<gO, blk, SM64>>>(pffh, pffl, wh + WT_2, wl + WT_2,
                                  b2v, px, ptmp, nullptr, nullptr, NTOK, DD, DFF);
        ln_kernel<<<NTOK, blk>>>(ptmp, g2 + (size_t)i*DD, be2 + (size_t)i*DD, px, pxh, pxl);
    }

    // final encoder LayerNorm -> output
    ln_kernel<<<NTOK, blk>>>(px, gf, bef, out, nullptr, nullptr);
}

// round 10
// speedup vs baseline: 1.6390x; 1.0188x over previous
#include <cuda_runtime.h>
#include <cuda_bf16.h>
#include <cstdint>
#include <cstddef>

#define BB   2
#define SS   1024
#define LL   2
#define HH   8
#define DD   512
#define DFF  2048
#define DKH  64
#define NTOK (BB*SS)      // 2048
#define NC   (SS/64)      // 16
#define BH   (BB*HH)      // 16
#define QSTR 1536
#define EPSF 1e-5f

typedef __nv_bfloat16 bf16;

// ---------------- scratch (device globals; no allocation) ----------------
__device__ __align__(128) float g_x   [NTOK*DD];
__device__ __align__(128) float g_tmp [NTOK*DD];
__device__ __align__(128) float g_qkv [NTOK*QSTR];
__device__ __align__(128) float g_kvc [BH*NC*DKH*DKH];
__device__ __align__(128) float g_st  [BH*NC*DKH*DKH];
__device__ __align__(128) bf16  g_xh  [NTOK*DD];
__device__ __align__(128) bf16  g_xl  [NTOK*DD];
__device__ __align__(128) bf16  g_atth[NTOK*DD];
__device__ __align__(128) bf16  g_attl[NTOK*DD];
__device__ __align__(128) bf16  g_ffh [NTOK*DFF];
__device__ __align__(128) bf16  g_ffl [NTOK*DFF];
#define WT_QKV 0
#define WT_O   (QSTR*DD)
#define WT_1   (WT_O + DD*DD)
#define WT_2   (WT_1 + DFF*DD)
#define WT_LAYER (WT_2 + DD*DFF)
__device__ __align__(128) bf16  g_wth [LL*WT_LAYER];
__device__ __align__(128) bf16  g_wtl [LL*WT_LAYER];
__device__ __align__(128) float g_bqkv[LL*QSTR];

// ============================ helpers ==================================
__device__ __forceinline__ void split_bf16(float v, bf16& h, bf16& l){
    h = __float2bfloat16(v);
    l = __float2bfloat16(v - __bfloat162float(h));
}
__device__ __forceinline__ uint32_t smem_u32(const void* p){
    uint32_t r;
    asm("{ .reg .u64 t; cvta.to.shared.u64 t, %1; cvt.u32.u64 %0, t; }" : "=r"(r) : "l"(p));
    return r;
}
__device__ __forceinline__ void mma_bf16(float* d, const uint32_t* a, const uint32_t* b){
    asm volatile(
        "mma.sync.aligned.m16n8k16.row.col.f32.bf16.bf16.f32 "
        "{%0,%1,%2,%3}, {%4,%5,%6,%7}, {%8,%9}, {%0,%1,%2,%3};\n"
        : "+f"(d[0]), "+f"(d[1]), "+f"(d[2]), "+f"(d[3])
        : "r"(a[0]), "r"(a[1]), "r"(a[2]), "r"(a[3]), "r"(b[0]), "r"(b[1]));
}
__device__ __forceinline__ void ldm4(uint32_t* r, uint32_t a){
    asm volatile("ldmatrix.sync.aligned.m8n8.x4.shared.b16 {%0,%1,%2,%3}, [%4];"
        : "=r"(r[0]), "=r"(r[1]), "=r"(r[2]), "=r"(r[3]) : "r"(a));
}
__device__ __forceinline__ void cp16(uint32_t dst, const void* src){
    asm volatile("cp.async.cg.shared.global [%0], [%1], 16;" :: "r"(dst), "l"(src));
}
#define CP_COMMIT() asm volatile("cp.async.commit_group;" ::: "memory")
#define CP_WAIT1()  asm volatile("cp.async.wait_group 1;" ::: "memory")

// ============== bf16 3-term GEMM: C[M,N] = A[M,K] @ B^T ====================
// A?,B?: bf16 [rows,K] row-major (hi/lo split). D = AhBh + AlBh + AhBl.
// 64 x 128 tiles, K-chunk 32, 8 warps, 3-stage cp.async ring, ldmatrix frags,
// term-major MMA ordering (breaks accumulator RAW chains), 2 CTAs/SM.
// EPI: 0=+bias->fp32; 1=+bias,relu->split bf16; 2=+bias+R->fp32
template<int EPI>
__global__ void __launch_bounds__(256, 2)
bf16_gemm(const bf16* __restrict__ Ah, const bf16* __restrict__ Al,
          const bf16* __restrict__ Bh, const bf16* __restrict__ Bl,
          const float* __restrict__ bias, const float* __restrict__ R,
          float* __restrict__ C, bf16* __restrict__ Ch, bf16* __restrict__ Cl,
          int M, int N, int K)
{
    constexpr int BM     = 64;
    constexpr int MT     = BM / 32;          // 2 warp m-subtiles
    constexpr int ABYTES = BM * 64;          // 4096
    constexpr int BBYTES = 128 * 64;         // 8192
    constexpr int CHUNK  = 2*ABYTES + 2*BBYTES;  // 24576
    extern __shared__ __align__(16) char dsm[];
    const uint32_t sbase = smem_u32(dsm);

    const int tid = threadIdx.x, lane = tid & 31, wid = tid >> 5;
    const int wm  = (wid >> 2) * 32, wn = (wid & 3) * 32;
    const int m0  = blockIdx.y * BM, n0 = blockIdx.x * 128;
    const int nch = K >> 5;

    // hoisted fragment offsets (within a stage)
    uint32_t offA[2][MT], offB[2][2];
#pragma unroll
    for (int ks = 0; ks < 2; ++ks){
        const int g = ks * 2 + (lane >> 4);
#pragma unroll
        for (int np = 0; np < 2; ++np){
            const int n = wn + np*16 + (lane & 15);
            offB[ks][np] = 2*ABYTES + n*64 + ((g ^ ((n >> 1) & 3)) << 4);
        }
#pragma unroll
        for (int mt = 0; mt < MT; ++mt){
            const int r = wm + mt*16 + (lane & 15);
            offA[ks][mt] = r*64 + ((g ^ ((r >> 1) & 3)) << 4);
        }
    }

    float acc[MT][4][4] = {};

    auto load_chunk = [&](int stage, int ch){
        const uint32_t bb = sbase + stage * CHUNK;
        const int koff = ch * 32;
        {   // A: 64 rows x 32 cols (h+l) = 256 cp16 each
            const int row = tid >> 2, g = tid & 3;
            const uint32_t dst = bb + row*64 + ((g ^ ((row >> 1) & 3)) << 4);
            const size_t so = (size_t)(m0 + row) * K + koff + g * 8;
            cp16(dst,          Ah + so);
            cp16(dst + ABYTES, Al + so);
        }
#pragma unroll
        for (int i = 0; i < 2; ++i){
            const int u = tid + i * 256, row = u >> 2, g = u & 3;
            const uint32_t dst = bb + 2*ABYTES + row*64 + ((g ^ ((row >> 1) & 3)) << 4);
            const size_t so = (size_t)(n0 + row) * K + koff + g * 8;
            cp16(dst,          Bh + so);
            cp16(dst + BBYTES, Bl + so);
        }
    };

    auto compute = [&](int stage){
        const uint32_t bb = sbase + stage * CHUNK;
#pragma unroll
        for (int ks = 0; ks < 2; ++ks){
            uint32_t bh[4][2], bl[4][2], ah[MT][4], al[MT][4];
#pragma unroll
            for (int np = 0; np < 2; ++np){
                uint32_t t[4];
                ldm4(t, bb + offB[ks][np]);
                bh[2*np][0]=t[0]; bh[2*np][1]=t[2]; bh[2*np+1][0]=t[1]; bh[2*np+1][1]=t[3];
                ldm4(t, bb + offB[ks][np] + BBYTES);
                bl[2*np][0]=t[0]; bl[2*np][1]=t[2]; bl[2*np+1][0]=t[1]; bl[2*np+1][1]=t[3];
            }
#pragma unroll
            for (int mt = 0; mt < MT; ++mt){
                ldm4(ah[mt], bb + offA[ks][mt]);
                ldm4(al[mt], bb + offA[ks][mt] + ABYTES);
            }
            // term-major: same-acc MMAs are 16 issues apart
#pragma unroll
            for (int mt = 0; mt < MT; ++mt)
#pragma unroll
                for (int nt = 0; nt < 4; ++nt) mma_bf16(acc[mt][nt], ah[mt], bh[nt]);
#pragma unroll
            for (int mt = 0; mt < MT; ++mt)
#pragma unroll
                for (int nt = 0; nt < 4; ++nt) mma_bf16(acc[mt][nt], al[mt], bh[nt]);
#pragma unroll
            for (int mt = 0; mt < MT; ++mt)
#pragma unroll
                for (int nt = 0; nt < 4; ++nt) mma_bf16(acc[mt][nt], ah[mt], bl[nt]);
        }
    };

    load_chunk(0, 0); CP_COMMIT();
    load_chunk(1, 1); CP_COMMIT();
    int cst = 0, lst = 2;
    for (int ch = 0; ch < nch; ++ch){
        CP_WAIT1();
        __syncthreads();
        if (ch + 2 < nch) load_chunk(lst, ch + 2);
        CP_COMMIT();
        compute(cst);
        cst = (cst == 2) ? 0 : cst + 1;
        lst = (lst == 2) ? 0 : lst + 1;
    }

    // epilogue: direct from accumulator fragments
#pragma unroll
    for (int mt = 0; mt < MT; ++mt){
#pragma unroll
        for (int nt = 0; nt < 4; ++nt){
            const int col = n0 + wn + nt*8 + (lane & 3) * 2;
            const float b0 = bias[col], b1 = bias[col + 1];
#pragma unroll
            for (int hf = 0; hf < 2; ++hf){
                const int row = m0 + wm + mt*16 + (lane >> 2) + hf*8;
                float v0 = acc[mt][nt][hf*2 + 0] + b0;
                float v1 = acc[mt][nt][hf*2 + 1] + b1;
                const size_t o = (size_t)row * N + col;
                if (EPI == 0){
                    *(float2*)&C[o] = make_float2(v0, v1);
                } else if (EPI == 1){
                    v0 = fmaxf(v0, 0.f); v1 = fmaxf(v1, 0.f);
                    bf16 h0, l0, h1, l1;
                    split_bf16(v0, h0, l0); split_bf16(v1, h1, l1);
                    *(__nv_bfloat162*)&Ch[o] = __nv_bfloat162(h0, h1);
                    *(__nv_bfloat162*)&Cl[o] = __nv_bfloat162(l0, l1);
                } else {
                    const float2 rr = *(const float2*)&R[o];
                    *(float2*)&C[o] = make_float2(v0 + rr.x, v1 + rr.y);
                }
            }
        }
    }
}

// ------- batched weight transpose+split: all 6 matrices, both layers -------
__global__ void transpose_split_all(
    const float* __restrict__ Wq, const float* __restrict__ Wk,
    const float* __restrict__ Wv, const float* __restrict__ Wo,
    const float* __restrict__ W1, const float* __restrict__ W2,
    bf16* __restrict__ wth, bf16* __restrict__ wtl)
{
    const int layer = blockIdx.y;
    int t = blockIdx.x;
    const float* S; int K, N; size_t doff;
    if (t < 1024){
        const int m = t >> 8; t &= 255;
        K = DD; N = DD;
        const float* s4[4] = {Wq, Wk, Wv, Wo};
        S = s4[m] + (size_t)layer * DD * DD;
        doff = (size_t)layer * WT_LAYER + (m < 3 ? (size_t)(WT_QKV + m*DD*DD) : (size_t)WT_O);
    } else if (t < 2048){
        t -= 1024; K = DD; N = DFF;
        S = W1 + (size_t)layer * DD * DFF;
        doff = (size_t)layer * WT_LAYER + WT_1;
    } else {
        t -= 2048; K = DFF; N = DD;
        S = W2 + (size_t)layer * DFF * DD;
        doff = (size_t)layer * WT_LAYER + WT_2;
    }
    const int ntx = N / 32;
    const int n0 = (t % ntx) * 32, k0 = (t / ntx) * 32;

    __shared__ float tt[32][33];
    const int x = threadIdx.x, y = threadIdx.y;   // 32 x 8
#pragma unroll
    for (int i = 0; i < 32; i += 8)
        tt[y + i][x] = S[(size_t)(k0 + y + i) * N + n0 + x];
    __syncthreads();
#pragma unroll
    for (int i = 0; i < 32; i += 8){
        const float v = tt[x][y + i];
        bf16 h, l; split_bf16(v, h, l);
        const size_t o = doff + (size_t)(n0 + y + i) * K + k0 + x;
        wth[o] = h; wtl[o] = l;
    }
}

// ---------------- split fp32 -> bf16 hi/lo ---------------------------------
__global__ void split_kernel(const float* __restrict__ X, bf16* __restrict__ Xh,
                             bf16* __restrict__ Xl)
{
    const int t = blockIdx.x * 256 + threadIdx.x;
    const float4 v = ((const float4*)X)[t];
    bf16 h0,l0,h1,l1,h2,l2,h3,l3;
    split_bf16(v.x,h0,l0); split_bf16(v.y,h1,l1);
    split_bf16(v.z,h2,l2); split_bf16(v.w,h3,l3);
    ((__nv_bfloat162*)Xh)[t*2+0] = __nv_bfloat162(h0,h1);
    ((__nv_bfloat162*)Xh)[t*2+1] = __nv_bfloat162(h2,h3);
    ((__nv_bfloat162*)Xl)[t*2+0] = __nv_bfloat162(l0,l1);
    ((__nv_bfloat162*)Xl)[t*2+1] = __nv_bfloat162(l2,l3);
}

__global__ void concat_bias(const float* __restrict__ bq, const float* __restrict__ bk,
                            const float* __restrict__ bv, float* __restrict__ dst)
{
    const int layer = blockIdx.y;
    const int t = blockIdx.x * 256 + threadIdx.x;
    float* d = dst + (size_t)layer * QSTR;
    if (t < 512)       d[t] = bq[layer*DD + t];
    else if (t < 1024) d[t] = bk[layer*DD + t - 512];
    else if (t < 1536) d[t] = bv[layer*DD + t - 1024];
}

// ---------------- LayerNorm (+ optional bf16 split outputs) ----------------
__global__ void ln_kernel(const float* __restrict__ X, const float* __restrict__ g,
                          const float* __restrict__ b, float* __restrict__ Y,
                          bf16* __restrict__ Yh, bf16* __restrict__ Yl)
{
    const int row = blockIdx.x;
    const int tid = threadIdx.x;
    const float* x = X + (size_t)row * DD;
    __shared__ float rs[256], rs2[256];
    float s = 0.f, s2 = 0.f;
    for (int j = tid; j < DD; j += 256) { float v = x[j]; s += v; s2 += v*v; }
    rs[tid] = s; rs2[tid] = s2;
    __syncthreads();
    for (int o = 128; o > 0; o >>= 1) {
        if (tid < o) { rs[tid] += rs[tid+o]; rs2[tid] += rs2[tid+o]; }
        __syncthreads();
    }
    const float m    = rs[0] * (1.f/DD);
    const float var  = rs2[0] * (1.f/DD) - m*m;
    const float rstd = rsqrtf(var + EPSF);
    for (int j = tid; j < DD; j += 256){
        const float v = (x[j] - m) * rstd * g[j] + b[j];
        Y[(size_t)row * DD + j] = v;
        if (Yh){
            bf16 h, l; split_bf16(v, h, l);
            Yh[(size_t)row * DD + j] = h;
            Yl[(size_t)row * DD + j] = l;
        }
    }
}

// ---------------- attention kernel 1: per-chunk K^T V [64x64] --------------
__global__ void attn_kvc_kernel(const float* __restrict__ QKV, float* __restrict__ kvc)
{
    __shared__ float ks[64][68], vs[64][68];
    const int blk = blockIdx.x;
    const int bh  = blk >> 4, c = blk & 15;
    const int b   = bh >> 3,  h = bh & 7;
    const int tid = threadIdx.x;
    const int j   = tid >> 2, base = (tid & 3) * 16;

    const size_t tok = (size_t)(b*SS + c*64 + j) * QSTR + h*DKH + base;
    const float* Kx = QKV + DD;
    const float* Vx = QKV + 2*DD;
#pragma unroll
    for (int u = 0; u < 4; ++u) {
        *(float4*)&ks[j][base + u*4] = *(const float4*)&Kx[tok + u*4];
        *(float4*)&vs[j][base + u*4] = *(const float4*)&Vx[tok + u*4];
    }
    __syncthreads();

    const int p = tid >> 2, qb = tid & 3;
    float acc[16] = {};
    for (int jj = 0; jj < 64; ++jj) {
        const float kp = ks[jj][p];
#pragma unroll
        for (int i = 0; i < 16; ++i) acc[i] += kp * vs[jj][qb + 4*i];
    }
    float* out = kvc + (size_t)blk * 4096 + p * 64;
#pragma unroll
    for (int i = 0; i < 16; ++i) out[qb + 4*i] = acc[i];
}

// ---------------- attention kernel 2: exclusive prefix over chunks ---------
__global__ void attn_prefix_kernel(const float* __restrict__ kvc, float* __restrict__ st)
{
    const int bh = blockIdx.x >> 4, r = blockIdx.x & 15;
    const int e  = threadIdx.x + r * 256;
    const size_t base = (size_t)bh * NC * 4096 + e;
    float v[NC];
#pragma unroll
    for (int c = 0; c < NC; ++c) v[c] = kvc[base + (size_t)c * 4096];
    float run = 0.f;
#pragma unroll
    for (int c = 0; c < NC; ++c) { st[base + (size_t)c * 4096] = run; run += v[c]; }
}

// ---------------- attention kernel 3: O = tril(QK^T)V + Q*state ------------
__global__ void attn_out_kernel(const float* __restrict__ QKV, const float* __restrict__ st,
                                bf16* __restrict__ Ath, bf16* __restrict__ Atl)
{
    extern __shared__ float sm[];
    float (*qs )[68] = (float(*)[68])sm;
    float (*ks )[68] = qs  + 64;
    float (*vs )[68] = ks  + 64;
    float (*ssm)[68] = vs  + 64;
    float (*sts)[68] = ssm + 64;

    const int blk = blockIdx.x;
    const int bh  = blk >> 4, c = blk & 15;
    const int b   = bh >> 3,  h = bh & 7;
    const int tid = threadIdx.x;
    const int row = tid >> 2, base = (tid & 3) * 16;

    const size_t tok = (size_t)(b*SS + c*64 + row) * QSTR + h*DKH + base;
    const float* stg = st + (size_t)blk * 4096 + row * 64 + base;
#pragma unroll
    for (int u = 0; u < 4; ++u) {
        *(float4*)&qs [row][base + u*4] = *(const float4*)&QKV[tok + u*4];
        *(float4*)&ks [row][base + u*4] = *(const float4*)&QKV[tok + DD + u*4];
        *(float4*)&vs [row][base + u*4] = *(const float4*)&QKV[tok + 2*DD + u*4];
        *(float4*)&sts[row][base + u*4] = *(const float4*)&stg[u*4];
    }
    __syncthreads();

    const int i = tid >> 2, j0 = tid & 3;
    for (int jj = 0; jj < 16; ++jj) {
        const int j = j0 + 4*jj;
        float d = 0.f;
#pragma unroll
        for (int p = 0; p < 64; ++p) d += qs[i][p] * ks[j][p];
        ssm[i][j] = (j <= i) ? d : 0.f;
    }
    __syncthreads();

    float acc[16] = {};
    for (int jj = 0; jj < 64; ++jj) {
        const float sij = ssm[i][jj];
        const float qip = qs[i][jj];
#pragma unroll
        for (int dd = 0; dd < 16; ++dd) {
            acc[dd] += sij * vs[jj][j0 + 4*dd];
            acc[dd] += qip * sts[jj][j0 + 4*dd];
        }
    }
    const size_t outp = (size_t)(b*SS + c*64 + i) * DD + h*DKH;
#pragma unroll
    for (int dd = 0; dd < 16; ++dd){
        bf16 h2, l2; split_bf16(acc[dd], h2, l2);
        Ath[outp + j0 + 4*dd] = h2;
        Atl[outp + j0 + 4*dd] = l2;
    }
}

// ---------------------------------------------------------------------------
extern "C" void kernel_launch(void* const* d_in, const int* in_sizes, int n_in,
                              void* d_out, int out_size)
{
    const float* src = (const float*)d_in[0];
    const float* Wq  = (const float*)d_in[1];
    const float* bq  = (const float*)d_in[2];
    const float* Wk  = (const float*)d_in[3];
    const float* bk  = (const float*)d_in[4];
    const float* Wv  = (const float*)d_in[5];
    const float* bv  = (const float*)d_in[6];
    const float* Wo  = (const float*)d_in[7];
    const float* bo  = (const float*)d_in[8];
    const float* W1  = (const float*)d_in[9];
    const float* b1  = (const float*)d_in[10];
    const float* W2  = (const float*)d_in[11];
    const float* b2  = (const float*)d_in[12];
    const float* g1  = (const float*)d_in[13];
    const float* be1 = (const float*)d_in[14];
    const float* g2  = (const float*)d_in[15];
    const float* be2 = (const float*)d_in[16];
    const float* gf  = (const float*)d_in[17];
    const float* bef = (const float*)d_in[18];
    float* out = (float*)d_out;

    float *px, *ptmp, *pqkv, *pkvc, *pst, *pbqkv;
    bf16 *pxh, *pxl, *path, *patl, *pffh, *pffl, *pwth, *pwtl;
    cudaGetSymbolAddress((void**)&px,    g_x);
    cudaGetSymbolAddress((void**)&ptmp,  g_tmp);
    cudaGetSymbolAddress((void**)&pqkv,  g_qkv);
    cudaGetSymbolAddress((void**)&pkvc,  g_kvc);
    cudaGetSymbolAddress((void**)&pst,   g_st);
    cudaGetSymbolAddress((void**)&pbqkv, g_bqkv);
    cudaGetSymbolAddress((void**)&pxh,   g_xh);
    cudaGetSymbolAddress((void**)&pxl,   g_xl);
    cudaGetSymbolAddress((void**)&path,  g_atth);
    cudaGetSymbolAddress((void**)&patl,  g_attl);
    cudaGetSymbolAddress((void**)&pffh,  g_ffh);
    cudaGetSymbolAddress((void**)&pffl,  g_ffl);
    cudaGetSymbolAddress((void**)&pwth,  g_wth);
    cudaGetSymbolAddress((void**)&pwtl,  g_wtl);

    static const int ATTN_SMEM = 5 * 64 * 68 * 4;        // 87,040 B
    static const int SMG = 3 * 24576;                    // 73,728 B
    cudaFuncSetAttribute(attn_out_kernel, cudaFuncAttributeMaxDynamicSharedMemorySize, ATTN_SMEM);
    cudaFuncSetAttribute(bf16_gemm<0>, cudaFuncAttributeMaxDynamicSharedMemorySize, SMG);
    cudaFuncSetAttribute(bf16_gemm<1>, cudaFuncAttributeMaxDynamicSharedMemorySize, SMG);
    cudaFuncSetAttribute(bf16_gemm<2>, cudaFuncAttributeMaxDynamicSharedMemorySize, SMG);

    // x = src (residual); split src for QKV GEMM
    cudaMemcpyAsync(px, src, (size_t)NTOK * DD * sizeof(float), cudaMemcpyDeviceToDevice, 0);
    split_kernel<<<NTOK*DD/4/256, 256>>>(src, pxh, pxl);

    // weight prep: single batched kernel + bias concat
    transpose_split_all<<<dim3(3072, LL), dim3(32, 8)>>>(Wq, Wk, Wv, Wo, W1, W2, pwth, pwtl);
    concat_bias<<<dim3(6, LL), 256>>>(bq, bk, bv, pbqkv);

    const dim3 gQKV(QSTR / 128, NTOK / 64);   // 12 x 32 = 384
    const dim3 gO  (DD   / 128, NTOK / 64);   // 4  x 32 = 128
    const dim3 gDF (DFF  / 128, NTOK / 64);   // 16 x 32 = 512
    const dim3 blk(256);

    for (int i = 0; i < LL; ++i) {
        bf16* wh = pwth + (size_t)i * WT_LAYER;
        bf16* wl = pwtl + (size_t)i * WT_LAYER;
        const float* bov = bo + (size_t)i*DD;
        const float* b1v = b1 + (size_t)i*DFF;
        const float* b2v = b2 + (size_t)i*DD;

        // fused QKV projection -> g_qkv fp32 [NTOK,1536]
        bf16_gemm<0><<<gQKV, blk, SMG>>>(pxh, pxl, wh + WT_QKV, wl + WT_QKV,
                                    pbqkv + (size_t)i*QSTR, nullptr,
                                    pqkv, nullptr, nullptr, NTOK, QSTR, DD);

        // chunked causal linear attention -> split bf16 att
        attn_kvc_kernel   <<<BH*NC, blk>>>(pqkv, pkvc);
        attn_prefix_kernel<<<BH*16, blk>>>(pkvc, pst);
        attn_out_kernel   <<<BH*NC, blk, ATTN_SMEM>>>(pqkv, pst, path, patl);

        // out proj + residual -> LN1 (LN emits fp32 + split)
        bf16_gemm<2><<<gO, blk, SMG>>>(path, patl, wh + WT_O, wl + WT_O,
                                  bov, px, ptmp, nullptr, nullptr, NTOK, DD, DD);
        ln_kernel<<<NTOK, blk>>>(ptmp, g1 + (size_t)i*DD, be1 + (size_t)i*DD, px, pxh, pxl);

        // FFN
        bf16_gemm<1><<<gDF, blk, SMG>>>(pxh, pxl, wh + WT_1, wl + WT_1,
                                   b1v, nullptr, nullptr, pffh, pffl, NTOK, DFF, DD);
        bf16_gemm<2><<<gO, blk, SMG>>>(pffh, pffl, wh + WT_2, wl + WT_2,
                                  b2v, px, ptmp, nullptr, nullptr, NTOK, DD, DFF);
        ln_kernel<<<NTOK, blk>>>(ptmp, g2 + (size_t)i*DD, be2 + (size_t)i*DD, px, pxh, pxl);
    }

    // final encoder LayerNorm -> output
    ln_kernel<<<NTOK, blk>>>(px, gf, bef, out, nullptr, nullptr);
}

// round 11
// speedup vs baseline: 1.7097x; 1.0431x over previous
#include <cuda_runtime.h>
#include <cuda_bf16.h>
#include <cstdint>
#include <cstddef>

#define BB   2
#define SS   1024
#define LL   2
#define HH   8
#define DD   512
#define DFF  2048
#define DKH  64
#define NTOK (BB*SS)      // 2048
#define NC   (SS/64)      // 16
#define BH   (BB*HH)      // 16
#define QSTR 1536
#define EPSF 1e-5f

typedef __nv_bfloat16 bf16;

// ---------------- scratch (device globals; no allocation) ----------------
__device__ __align__(128) float g_x   [NTOK*DD];
__device__ __align__(128) float g_tmp [NTOK*DD];
__device__ __align__(128) float g_tmp2[NTOK*DD];
__device__ __align__(128) float g_qkv [NTOK*QSTR];
__device__ __align__(128) float g_kvc [BH*NC*DKH*DKH];
__device__ __align__(128) float g_st  [BH*NC*DKH*DKH];
__device__ __align__(128) bf16  g_xh  [NTOK*DD];
__device__ __align__(128) bf16  g_xl  [NTOK*DD];
__device__ __align__(128) bf16  g_atth[NTOK*DD];
__device__ __align__(128) bf16  g_attl[NTOK*DD];
__device__ __align__(128) bf16  g_ffh [NTOK*DFF];
__device__ __align__(128) bf16  g_ffl [NTOK*DFF];
#define WT_QKV 0
#define WT_O   (QSTR*DD)
#define WT_1   (WT_O + DD*DD)
#define WT_2   (WT_1 + DFF*DD)
#define WT_LAYER (WT_2 + DD*DFF)
__device__ __align__(128) bf16  g_wth [LL*WT_LAYER];
__device__ __align__(128) bf16  g_wtl [LL*WT_LAYER];
__device__ __align__(128) float g_bqkv[LL*QSTR];

// ============================ helpers ==================================
__device__ __forceinline__ void split_bf16(float v, bf16& h, bf16& l){
    h = __float2bfloat16(v);
    l = __float2bfloat16(v - __bfloat162float(h));
}
__device__ __forceinline__ uint32_t smem_u32(const void* p){
    uint32_t r;
    asm("{ .reg .u64 t; cvta.to.shared.u64 t, %1; cvt.u32.u64 %0, t; }" : "=r"(r) : "l"(p));
    return r;
}
__device__ __forceinline__ void mma_bf16(float* d, const uint32_t* a, const uint32_t* b){
    asm volatile(
        "mma.sync.aligned.m16n8k16.row.col.f32.bf16.bf16.f32 "
        "{%0,%1,%2,%3}, {%4,%5,%6,%7}, {%8,%9}, {%0,%1,%2,%3};\n"
        : "+f"(d[0]), "+f"(d[1]), "+f"(d[2]), "+f"(d[3])
        : "r"(a[0]), "r"(a[1]), "r"(a[2]), "r"(a[3]), "r"(b[0]), "r"(b[1]));
}
__device__ __forceinline__ void ldm4(uint32_t* r, uint32_t a){
    asm volatile("ldmatrix.sync.aligned.m8n8.x4.shared.b16 {%0,%1,%2,%3}, [%4];"
        : "=r"(r[0]), "=r"(r[1]), "=r"(r[2]), "=r"(r[3]) : "r"(a));
}
__device__ __forceinline__ void cp16(uint32_t dst, const void* src){
    asm volatile("cp.async.cg.shared.global [%0], [%1], 16;" :: "r"(dst), "l"(src));
}
#define CP_COMMIT() asm volatile("cp.async.commit_group;" ::: "memory")
#define CP_WAIT1()  asm volatile("cp.async.wait_group 1;" ::: "memory")

// ============== bf16 3-term GEMM: C[M,N] = A[M,K] @ B^T ====================
// A?,B?: bf16 [rows,K] row-major (hi/lo split). D = AhBh + AlBh + AhBl.
// 64x128 tiles, K-chunk 32, 8 warps, 3-stage cp.async ring, ldmatrix frags,
// term-major MMA order, up to 3 CTAs/SM. gridDim.z=2 => split-K halves
// (half z writes raw partial to C (z=0) or C2 (z=1)).
// EPI: 0=+bias->fp32; 1=+bias,relu->split bf16; 2=+bias+R->fp32; 3=raw->fp32
template<int EPI>
__global__ void __launch_bounds__(256, 3)
bf16_gemm(const bf16* __restrict__ Ah, const bf16* __restrict__ Al,
          const bf16* __restrict__ Bh, const bf16* __restrict__ Bl,
          const float* __restrict__ bias, const float* __restrict__ R,
          float* __restrict__ C, bf16* __restrict__ Ch, bf16* __restrict__ Cl,
          float* __restrict__ C2, int M, int N, int K, int Kloop)
{
    constexpr int BM     = 64;
    constexpr int MT     = 2;
    constexpr int ABYTES = BM * 64;              // 4096
    constexpr int BBYTES = 128 * 64;             // 8192
    constexpr int CHUNK  = 2*ABYTES + 2*BBYTES;  // 24576
    extern __shared__ __align__(16) char dsm[];
    const uint32_t sbase = smem_u32(dsm);

    const int tid = threadIdx.x, lane = tid & 31, wid = tid >> 5;
    const int wm  = (wid >> 2) * 32, wn = (wid & 3) * 32;
    const int m0  = blockIdx.y * BM, n0 = blockIdx.x * 128;
    const int koff = blockIdx.z * Kloop;
    const int nch = Kloop >> 5;

    // hoisted fragment offsets (within a stage)
    uint32_t offA[2][MT], offB[2][2];
#pragma unroll
    for (int ks = 0; ks < 2; ++ks){
        const int g = ks * 2 + (lane >> 4);
#pragma unroll
        for (int np = 0; np < 2; ++np){
            const int n = wn + np*16 + (lane & 15);
            offB[ks][np] = 2*ABYTES + n*64 + ((g ^ ((n >> 1) & 3)) << 4);
        }
#pragma unroll
        for (int mt = 0; mt < MT; ++mt){
            const int r = wm + mt*16 + (lane & 15);
            offA[ks][mt] = r*64 + ((g ^ ((r >> 1) & 3)) << 4);
        }
    }

    float acc[MT][4][4] = {};

    auto load_chunk = [&](int stage, int ch){
        const uint32_t bb = sbase + stage * CHUNK;
        const int kc = koff + ch * 32;
        {
            const int row = tid >> 2, g = tid & 3;
            const uint32_t dst = bb + row*64 + ((g ^ ((row >> 1) & 3)) << 4);
            const size_t so = (size_t)(m0 + row) * K + kc + g * 8;
            cp16(dst,          Ah + so);
            cp16(dst + ABYTES, Al + so);
        }
#pragma unroll
        for (int i = 0; i < 2; ++i){
            const int u = tid + i * 256, row = u >> 2, g = u & 3;
            const uint32_t dst = bb + 2*ABYTES + row*64 + ((g ^ ((row >> 1) & 3)) << 4);
            const size_t so = (size_t)(n0 + row) * K + kc + g * 8;
            cp16(dst,          Bh + so);
            cp16(dst + BBYTES, Bl + so);
        }
    };

    auto compute = [&](int stage){
        const uint32_t bb = sbase + stage * CHUNK;
#pragma unroll
        for (int ks = 0; ks < 2; ++ks){
            uint32_t bh[4][2], bl[4][2], ah[MT][4], al[MT][4];
#pragma unroll
            for (int np = 0; np < 2; ++np){
                uint32_t t[4];
                ldm4(t, bb + offB[ks][np]);
                bh[2*np][0]=t[0]; bh[2*np][1]=t[2]; bh[2*np+1][0]=t[1]; bh[2*np+1][1]=t[3];
                ldm4(t, bb + offB[ks][np] + BBYTES);
                bl[2*np][0]=t[0]; bl[2*np][1]=t[2]; bl[2*np+1][0]=t[1]; bl[2*np+1][1]=t[3];
            }
#pragma unroll
            for (int mt = 0; mt < MT; ++mt){
                ldm4(ah[mt], bb + offA[ks][mt]);
                ldm4(al[mt], bb + offA[ks][mt] + ABYTES);
            }
#pragma unroll
            for (int mt = 0; mt < MT; ++mt)
#pragma unroll
                for (int nt = 0; nt < 4; ++nt) mma_bf16(acc[mt][nt], ah[mt], bh[nt]);
#pragma unroll
            for (int mt = 0; mt < MT; ++mt)
#pragma unroll
                for (int nt = 0; nt < 4; ++nt) mma_bf16(acc[mt][nt], al[mt], bh[nt]);
#pragma unroll
            for (int mt = 0; mt < MT; ++mt)
#pragma unroll
                for (int nt = 0; nt < 4; ++nt) mma_bf16(acc[mt][nt], ah[mt], bl[nt]);
        }
    };

    load_chunk(0, 0); CP_COMMIT();
    load_chunk(1, 1); CP_COMMIT();
    int cst = 0, lst = 2;
    for (int ch = 0; ch < nch; ++ch){
        CP_WAIT1();
        __syncthreads();
        if (ch + 2 < nch) load_chunk(lst, ch + 2);
        CP_COMMIT();
        compute(cst);
        cst = (cst == 2) ? 0 : cst + 1;
        lst = (lst == 2) ? 0 : lst + 1;
    }

    float* Cw = (EPI == 3 && blockIdx.z) ? C2 : C;

    // epilogue: direct from accumulator fragments
#pragma unroll
    for (int mt = 0; mt < MT; ++mt){
#pragma unroll
        for (int nt = 0; nt < 4; ++nt){
            const int col = n0 + wn + nt*8 + (lane & 3) * 2;
            float b0 = 0.f, b1 = 0.f;
            if (EPI != 3){ b0 = bias[col]; b1 = bias[col + 1]; }
#pragma unroll
            for (int hf = 0; hf < 2; ++hf){
                const int row = m0 + wm + mt*16 + (lane >> 2) + hf*8;
                float v0 = acc[mt][nt][hf*2 + 0] + b0;
                float v1 = acc[mt][nt][hf*2 + 1] + b1;
                const size_t o = (size_t)row * N + col;
                if (EPI == 0 || EPI == 3){
                    *(float2*)&Cw[o] = make_float2(v0, v1);
                } else if (EPI == 1){
                    v0 = fmaxf(v0, 0.f); v1 = fmaxf(v1, 0.f);
                    bf16 h0, l0, h1, l1;
                    split_bf16(v0, h0, l0); split_bf16(v1, h1, l1);
                    *(__nv_bfloat162*)&Ch[o] = __nv_bfloat162(h0, h1);
                    *(__nv_bfloat162*)&Cl[o] = __nv_bfloat162(l0, l1);
                } else {
                    const float2 rr = *(const float2*)&R[o];
                    *(float2*)&Cw[o] = make_float2(v0 + rr.x, v1 + rr.y);
                }
            }
        }
    }
}

// ------- batched weight transpose+split: all 6 matrices, both layers -------
__global__ void transpose_split_all(
    const float* __restrict__ Wq, const float* __restrict__ Wk,
    const float* __restrict__ Wv, const float* __restrict__ Wo,
    const float* __restrict__ W1, const float* __restrict__ W2,
    bf16* __restrict__ wth, bf16* __restrict__ wtl)
{
    const int layer = blockIdx.y;
    int t = blockIdx.x;
    const float* S; int K, N; size_t doff;
    if (t < 1024){
        const int m = t >> 8; t &= 255;
        K = DD; N = DD;
        const float* s4[4] = {Wq, Wk, Wv, Wo};
        S = s4[m] + (size_t)layer * DD * DD;
        doff = (size_t)layer * WT_LAYER + (m < 3 ? (size_t)(WT_QKV + m*DD*DD) : (size_t)WT_O);
    } else if (t < 2048){
        t -= 1024; K = DD; N = DFF;
        S = W1 + (size_t)layer * DD * DFF;
        doff = (size_t)layer * WT_LAYER + WT_1;
    } else {
        t -= 2048; K = DFF; N = DD;
        S = W2 + (size_t)layer * DFF * DD;
        doff = (size_t)layer * WT_LAYER + WT_2;
    }
    const int ntx = N / 32;
    const int n0 = (t % ntx) * 32, k0 = (t / ntx) * 32;

    __shared__ float tt[32][33];
    const int x = threadIdx.x, y = threadIdx.y;   // 32 x 8
#pragma unroll
    for (int i = 0; i < 32; i += 8)
        tt[y + i][x] = S[(size_t)(k0 + y + i) * N + n0 + x];
    __syncthreads();
#pragma unroll
    for (int i = 0; i < 32; i += 8){
        const float v = tt[x][y + i];
        bf16 h, l; split_bf16(v, h, l);
        const size_t o = doff + (size_t)(n0 + y + i) * K + k0 + x;
        wth[o] = h; wtl[o] = l;
    }
}

// -------- split fp32 -> bf16 hi/lo, also copies into residual buffer -------
__global__ void split_kernel(const float* __restrict__ X, float* __restrict__ Y,
                             bf16* __restrict__ Xh, bf16* __restrict__ Xl)
{
    const int t = blockIdx.x * 256 + threadIdx.x;
    const float4 v = ((const float4*)X)[t];
    ((float4*)Y)[t] = v;
    bf16 h0,l0,h1,l1,h2,l2,h3,l3;
    split_bf16(v.x,h0,l0); split_bf16(v.y,h1,l1);
    split_bf16(v.z,h2,l2); split_bf16(v.w,h3,l3);
    ((__nv_bfloat162*)Xh)[t*2+0] = __nv_bfloat162(h0,h1);
    ((__nv_bfloat162*)Xh)[t*2+1] = __nv_bfloat162(h2,h3);
    ((__nv_bfloat162*)Xl)[t*2+0] = __nv_bfloat162(l0,l1);
    ((__nv_bfloat162*)Xl)[t*2+1] = __nv_bfloat162(l2,l3);
}

__global__ void concat_bias(const float* __restrict__ bq, const float* __restrict__ bk,
                            const float* __restrict__ bv, float* __restrict__ dst)
{
    const int layer = blockIdx.y;
    const int t = blockIdx.x * 256 + threadIdx.x;
    float* d = dst + (size_t)layer * QSTR;
    if (t < 512)       d[t] = bq[layer*DD + t];
    else if (t < 1024) d[t] = bk[layer*DD + t - 512];
    else if (t < 1536) d[t] = bv[layer*DD + t - 1024];
}

// ------- LayerNorm with fused combine: x = X + X2? + bias2? + R? -----------
// (optional bf16 split outputs). One block per row, 2 elements per thread.
__global__ void ln_kernel(const float* __restrict__ X, const float* __restrict__ X2,
                          const float* __restrict__ bias2, const float* __restrict__ R,
                          const float* __restrict__ g, const float* __restrict__ b,
                          float* __restrict__ Y, bf16* __restrict__ Yh,
                          bf16* __restrict__ Yl)
{
    const int row = blockIdx.x;
    const int tid = threadIdx.x;
    const size_t base = (size_t)row * DD;
    __shared__ float rs[256], rs2[256];
    float xv[2];
    float s = 0.f, s2 = 0.f;
#pragma unroll
    for (int u = 0; u < 2; ++u){
        const int j = tid + u * 256;
        float v = X[base + j];
        if (X2)    v += X2[base + j];
        if (bias2) v += bias2[j];
        if (R)     v += R[base + j];
        xv[u] = v; s += v; s2 += v*v;
    }
    rs[tid] = s; rs2[tid] = s2;
    __syncthreads();
    for (int o = 128; o > 0; o >>= 1) {
        if (tid < o) { rs[tid] += rs[tid+o]; rs2[tid] += rs2[tid+o]; }
        __syncthreads();
    }
    const float m    = rs[0] * (1.f/DD);
    const float var  = rs2[0] * (1.f/DD) - m*m;
    const float rstd = rsqrtf(var + EPSF);
#pragma unroll
    for (int u = 0; u < 2; ++u){
        const int j = tid + u * 256;
        const float v = (xv[u] - m) * rstd * g[j] + b[j];
        Y[base + j] = v;
        if (Yh){
            bf16 h, l; split_bf16(v, h, l);
            Yh[base + j] = h;
            Yl[base + j] = l;
        }
    }
}

// ---------------- attention kernel 1: per-chunk K^T V [64x64] --------------
__global__ void attn_kvc_kernel(const float* __restrict__ QKV, float* __restrict__ kvc)
{
    __shared__ float ks[64][68], vs[64][68];
    const int blk = blockIdx.x;
    const int bh  = blk >> 4, c = blk & 15;
    const int b   = bh >> 3,  h = bh & 7;
    const int tid = threadIdx.x;
    const int j   = tid >> 2, base = (tid & 3) * 16;

    const size_t tok = (size_t)(b*SS + c*64 + j) * QSTR + h*DKH + base;
    const float* Kx = QKV + DD;
    const float* Vx = QKV + 2*DD;
#pragma unroll
    for (int u = 0; u < 4; ++u) {
        *(float4*)&ks[j][base + u*4] = *(const float4*)&Kx[tok + u*4];
        *(float4*)&vs[j][base + u*4] = *(const float4*)&Vx[tok + u*4];
    }
    __syncthreads();

    const int p = tid >> 2, qb = tid & 3;
    float acc[16] = {};
    for (int jj = 0; jj < 64; ++jj) {
        const float kp = ks[jj][p];
#pragma unroll
        for (int i = 0; i < 16; ++i) acc[i] += kp * vs[jj][qb + 4*i];
    }
    float* out = kvc + (size_t)blk * 4096 + p * 64;
#pragma unroll
    for (int i = 0; i < 16; ++i) out[qb + 4*i] = acc[i];
}

// ---------------- attention kernel 2: exclusive prefix over chunks ---------
__global__ void attn_prefix_kernel(const float* __restrict__ kvc, float* __restrict__ st)
{
    const int bh = blockIdx.x >> 4, r = blockIdx.x & 15;
    const int e  = threadIdx.x + r * 256;
    const size_t base = (size_t)bh * NC * 4096 + e;
    float v[NC];
#pragma unroll
    for (int c = 0; c < NC; ++c) v[c] = kvc[base + (size_t)c * 4096];
    float run = 0.f;
#pragma unroll
    for (int c = 0; c < NC; ++c) { st[base + (size_t)c * 4096] = run; run += v[c]; }
}

// ---------------- attention kernel 3: O = tril(QK^T)V + Q*state ------------
__global__ void attn_out_kernel(const float* __restrict__ QKV, const float* __restrict__ st,
                                bf16* __restrict__ Ath, bf16* __restrict__ Atl)
{
    extern __shared__ float sm[];
    float (*qs )[68] = (float(*)[68])sm;
    float (*ks )[68] = qs  + 64;
    float (*vs )[68] = ks  + 64;
    float (*ssm)[68] = vs  + 64;
    float (*sts)[68] = ssm + 64;

    const int blk = blockIdx.x;
    const int bh  = blk >> 4, c = blk & 15;
    const int b   = bh >> 3,  h = bh & 7;
    const int tid = threadIdx.x;
    const int row = tid >> 2, base = (tid & 3) * 16;

    const size_t tok = (size_t)(b*SS + c*64 + row) * QSTR + h*DKH + base;
    const float* stg = st + (size_t)blk * 4096 + row * 64 + base;
#pragma unroll
    for (int u = 0; u < 4; ++u) {
        *(float4*)&qs [row][base + u*4] = *(const float4*)&QKV[tok + u*4];
        *(float4*)&ks [row][base + u*4] = *(const float4*)&QKV[tok + DD + u*4];
        *(float4*)&vs [row][base + u*4] = *(const float4*)&QKV[tok + 2*DD + u*4];
        *(float4*)&sts[row][base + u*4] = *(const float4*)&stg[u*4];
    }
    __syncthreads();

    const int i = tid >> 2, j0 = tid & 3;
    for (int jj = 0; jj < 16; ++jj) {
        const int j = j0 + 4*jj;
        float d = 0.f;
#pragma unroll
        for (int p = 0; p < 64; ++p) d += qs[i][p] * ks[j][p];
        ssm[i][j] = (j <= i) ? d : 0.f;
    }
    __syncthreads();

    float acc[16] = {};
    for (int jj = 0; jj < 64; ++jj) {
        const float sij = ssm[i][jj];
        const float qip = qs[i][jj];
#pragma unroll
        for (int dd = 0; dd < 16; ++dd) {
            acc[dd] += sij * vs[jj][j0 + 4*dd];
            acc[dd] += qip * sts[jj][j0 + 4*dd];
        }
    }
    const size_t outp = (size_t)(b*SS + c*64 + i) * DD + h*DKH;
#pragma unroll
    for (int dd = 0; dd < 16; ++dd){
        bf16 h2, l2; split_bf16(acc[dd], h2, l2);
        Ath[outp + j0 + 4*dd] = h2;
        Atl[outp + j0 + 4*dd] = l2;
    }
}

// ---------------------------------------------------------------------------
extern "C" void kernel_launch(void* const* d_in, const int* in_sizes, int n_in,
                              void* d_out, int out_size)
{
    const float* src = (const float*)d_in[0];
    const float* Wq  = (const float*)d_in[1];
    const float* bq  = (const float*)d_in[2];
    const float* Wk  = (const float*)d_in[3];
    const float* bk  = (const float*)d_in[4];
    const float* Wv  = (const float*)d_in[5];
    const float* bv  = (const float*)d_in[6];
    const float* Wo  = (const float*)d_in[7];
    const float* bo  = (const float*)d_in[8];
    const float* W1  = (const float*)d_in[9];
    const float* b1  = (const float*)d_in[10];
    const float* W2  = (const float*)d_in[11];
    const float* b2  = (const float*)d_in[12];
    const float* g1  = (const float*)d_in[13];
    const float* be1 = (const float*)d_in[14];
    const float* g2  = (const float*)d_in[15];
    const float* be2 = (const float*)d_in[16];
    const float* gf  = (const float*)d_in[17];
    const float* bef = (const float*)d_in[18];
    float* out = (float*)d_out;

    float *px, *ptmp, *ptmp2, *pqkv, *pkvc, *pst, *pbqkv;
    bf16 *pxh, *pxl, *path, *patl, *pffh, *pffl, *pwth, *pwtl;
    cudaGetSymbolAddress((void**)&px,    g_x);
    cudaGetSymbolAddress((void**)&ptmp,  g_tmp);
    cudaGetSymbolAddress((void**)&ptmp2, g_tmp2);
    cudaGetSymbolAddress((void**)&pqkv,  g_qkv);
    cudaGetSymbolAddress((void**)&pkvc,  g_kvc);
    cudaGetSymbolAddress((void**)&pst,   g_st);
    cudaGetSymbolAddress((void**)&pbqkv, g_bqkv);
    cudaGetSymbolAddress((void**)&pxh,   g_xh);
    cudaGetSymbolAddress((void**)&pxl,   g_xl);
    cudaGetSymbolAddress((void**)&path,  g_atth);
    cudaGetSymbolAddress((void**)&patl,  g_attl);
    cudaGetSymbolAddress((void**)&pffh,  g_ffh);
    cudaGetSymbolAddress((void**)&pffl,  g_ffl);
    cudaGetSymbolAddress((void**)&pwth,  g_wth);
    cudaGetSymbolAddress((void**)&pwtl,  g_wtl);

    static const int ATTN_SMEM = 5 * 64 * 68 * 4;        // 87,040 B
    static const int SMG = 3 * 24576;                    // 73,728 B
    cudaFuncSetAttribute(attn_out_kernel, cudaFuncAttributeMaxDynamicSharedMemorySize, ATTN_SMEM);
    cudaFuncSetAttribute(bf16_gemm<0>, cudaFuncAttributeMaxDynamicSharedMemorySize, SMG);
    cudaFuncSetAttribute(bf16_gemm<1>, cudaFuncAttributeMaxDynamicSharedMemorySize, SMG);
    cudaFuncSetAttribute(bf16_gemm<3>, cudaFuncAttributeMaxDynamicSharedMemorySize, SMG);

    // residual = src, split src for QKV GEMM (fused)
    split_kernel<<<NTOK*DD/4/256, 256>>>(src, px, pxh, pxl);

    // weight prep: single batched kernel + bias concat
    transpose_split_all<<<dim3(3072, LL), dim3(32, 8)>>>(Wq, Wk, Wv, Wo, W1, W2, pwth, pwtl);
    concat_bias<<<dim3(6, LL), 256>>>(bq, bk, bv, pbqkv);

    const dim3 gQKV(QSTR / 128, NTOK / 64, 1);   // 384
    const dim3 gOS (DD   / 128, NTOK / 64, 2);   // 256 (split-K)
    const dim3 gDF (DFF  / 128, NTOK / 64, 1);   // 512
    const dim3 blk(256);

    for (int i = 0; i < LL; ++i) {
        bf16* wh = pwth + (size_t)i * WT_LAYER;
        bf16* wl = pwtl + (size_t)i * WT_LAYER;
        const float* bov = bo + (size_t)i*DD;
        const float* b1v = b1 + (size_t)i*DFF;
        const float* b2v = b2 + (size_t)i*DD;

        // fused QKV projection -> g_qkv fp32 [NTOK,1536]
        bf16_gemm<0><<<gQKV, blk, SMG>>>(pxh, pxl, wh + WT_QKV, wl + WT_QKV,
                                    pbqkv + (size_t)i*QSTR, nullptr,
                                    pqkv, nullptr, nullptr, nullptr, NTOK, QSTR, DD, DD);

        // chunked causal linear attention -> split bf16 att
        attn_kvc_kernel   <<<BH*NC, blk>>>(pqkv, pkvc);
        attn_prefix_kernel<<<BH*16, blk>>>(pkvc, pst);
        attn_out_kernel   <<<BH*NC, blk, ATTN_SMEM>>>(pqkv, pst, path, patl);

        // out proj (split-K=2, raw partials) -> LN1 combines (+bo, +residual)
        bf16_gemm<3><<<gOS, blk, SMG>>>(path, patl, wh + WT_O, wl + WT_O,
                                  nullptr, nullptr, ptmp, nullptr, nullptr, ptmp2,
                                  NTOK, DD, DD, DD/2);
        ln_kernel<<<NTOK, blk>>>(ptmp, ptmp2, bov, px,
                                 g1 + (size_t)i*DD, be1 + (size_t)i*DD, px, pxh, pxl);

        // FFN: FF1 (relu, split bf16 out), FF2 split-K=2 -> LN2 combines
        bf16_gemm<1><<<gDF, blk, SMG>>>(pxh, pxl, wh + WT_1, wl + WT_1,
                                   b1v, nullptr, nullptr, pffh, pffl, nullptr,
                                   NTOK, DFF, DD, DD);
        bf16_gemm<3><<<gOS, blk, SMG>>>(pffh, pffl, wh + WT_2, wl + WT_2,
                                  nullptr, nullptr, ptmp, nullptr, nullptr, ptmp2,
                                  NTOK, DD, DFF, DFF/2);
        ln_kernel<<<NTOK, blk>>>(ptmp, ptmp2, b2v, px,
                                 g2 + (size_t)i*DD, be2 + (size_t)i*DD, px, pxh, pxl);
    }

    // final encoder LayerNorm -> output
    ln_kernel<<<NTOK, blk>>>(px, nullptr, nullptr, nullptr, gf, bef, out, nullptr, nullptr);
}